// round 2
// baseline (speedup 1.0000x reference)
#include <cuda_runtime.h>

#define D_MODEL 1024
#define N_HEADS 16
#define D_HEAD  64
#define BATCH   4
#define SEQ     2048

// Scratch (allocation-free rule: __device__ globals)
__device__ float g_q[BATCH * N_HEADS * SEQ * D_HEAD];     // [B,H,T,Dh]
__device__ float g_k[BATCH * N_HEADS * SEQ * D_HEAD];
__device__ float g_v[BATCH * N_HEADS * SEQ * D_HEAD];
__device__ float g_attn[BATCH * SEQ * D_MODEL];           // [B,T,C]

// ---------------------------------------------------------------------------
// SGEMM: C[M,N] = A[M,K] @ B[K,N] + bias[N]
// BM=BN=128, BK=16, 256 threads, 8x8 per thread (split-tile 4+4 layout).
// mode 0: A = g_attn (out proj), store plain to C
// mode 1: A = A_ext (x), scatter epilogue into g_q/g_k/g_v with [B,H,T,Dh]
// ---------------------------------------------------------------------------
#define BM 128
#define BN 128
#define BK 16

__global__ __launch_bounds__(256) void gemm_kernel(
    const float* __restrict__ A_ext, const float* __restrict__ B,
    const float* __restrict__ bias, float* __restrict__ C,
    int N, int K, int mode)
{
    __shared__ float As[BK][BM];
    __shared__ float Bs[BK][BN];

    const float* A = (mode == 1) ? A_ext : g_attn;

    const int tid = threadIdx.x;
    const int tx = tid & 15;         // 16 col-threads
    const int ty = tid >> 4;         // 16 row-threads
    const int bx = blockIdx.x;       // N tile
    const int by = blockIdx.y;       // M tile

    const float* Ab = A + (size_t)by * BM * K;
    const float* Bb = B + (size_t)bx * BN;

    // load mapping
    const int aRow = tid >> 2;              // 0..63
    const int aCol = (tid & 3) << 2;        // 0,4,8,12
    const int bRow = tid >> 5;              // 0..7
    const int bCol = (tid & 31) << 2;       // 0..124

    float acc[8][8];
#pragma unroll
    for (int i = 0; i < 8; i++)
#pragma unroll
        for (int j = 0; j < 8; j++) acc[i][j] = 0.f;

    for (int k0 = 0; k0 < K; k0 += BK) {
        float4 a0 = *(const float4*)(Ab + (size_t)aRow * K + k0 + aCol);
        float4 a1 = *(const float4*)(Ab + (size_t)(aRow + 64) * K + k0 + aCol);
        As[aCol + 0][aRow] = a0.x; As[aCol + 1][aRow] = a0.y;
        As[aCol + 2][aRow] = a0.z; As[aCol + 3][aRow] = a0.w;
        As[aCol + 0][aRow + 64] = a1.x; As[aCol + 1][aRow + 64] = a1.y;
        As[aCol + 2][aRow + 64] = a1.z; As[aCol + 3][aRow + 64] = a1.w;

        float4 b0 = *(const float4*)(Bb + (size_t)(k0 + bRow) * N + bCol);
        float4 b1 = *(const float4*)(Bb + (size_t)(k0 + bRow + 8) * N + bCol);
        *(float4*)&Bs[bRow][bCol] = b0;
        *(float4*)&Bs[bRow + 8][bCol] = b1;
        __syncthreads();

#pragma unroll
        for (int kk = 0; kk < BK; kk++) {
            float ra[8], rb[8];
            *(float4*)&ra[0] = *(const float4*)&As[kk][ty << 2];
            *(float4*)&ra[4] = *(const float4*)&As[kk][(ty << 2) + 64];
            *(float4*)&rb[0] = *(const float4*)&Bs[kk][tx << 2];
            *(float4*)&rb[4] = *(const float4*)&Bs[kk][(tx << 2) + 64];
#pragma unroll
            for (int i = 0; i < 8; i++)
#pragma unroll
                for (int j = 0; j < 8; j++)
                    acc[i][j] = fmaf(ra[i], rb[j], acc[i][j]);
        }
        __syncthreads();
    }

    // epilogue
#pragma unroll
    for (int i = 0; i < 8; i++) {
        int r = by * BM + (ty << 2) + (i & 3) + ((i >> 2) << 6);
#pragma unroll
        for (int j = 0; j < 8; j++) {
            int c = bx * BN + (tx << 2) + (j & 3) + ((j >> 2) << 6);
            float val = acc[i][j] + bias[c];
            if (mode == 0) {
                C[(size_t)r * N + c] = val;
            } else {
                int b = r >> 11, t = r & 2047;       // SEQ = 2048
                int s = c >> 10, rem = c & 1023;     // D_MODEL = 1024
                int h = rem >> 6, d = rem & 63;
                float* dst = (s == 0) ? g_q : (s == 1) ? g_k : g_v;
                dst[((((size_t)b << 4) + h) * SEQ + t) * D_HEAD + d] = val;
            }
        }
    }
}

// ---------------------------------------------------------------------------
// Flash attention, fp32. One block = one 64-row Q tile of one (b,h).
// 256 threads = 16x16 grid, 4x4 of S/O per thread.
// Tile buffers live in DYNAMIC shared memory (67.3 KB > 48 KB static cap).
// Layout (floats):
//   Qt [64][65]  [d][q-row]   offset 0
//   Kt [64][65]  [d][k-col]   offset 64*65
//   Vs [64][68]  [k-row][d]   offset 2*64*65
//   Ps [64][68]  [q-row][k]   offset 2*64*65 + 64*68
// ---------------------------------------------------------------------------
#define ATTN_SMEM_FLOATS (2*64*65 + 2*64*68)
#define ATTN_SMEM_BYTES  (ATTN_SMEM_FLOATS * 4)

__global__ __launch_bounds__(256) void attn_kernel()
{
    extern __shared__ float sm[];
    float (*Qt)[65] = (float(*)[65])(sm);
    float (*Kt)[65] = (float(*)[65])(sm + 64*65);
    float (*Vs)[68] = (float(*)[68])(sm + 2*64*65);
    float (*Ps)[68] = (float(*)[68])(sm + 2*64*65 + 64*68);
    __shared__ float m_row[64], l_row[64], alpha_s[64];

    const int tid  = threadIdx.x;
    const int tx   = tid & 15;
    const int ty   = tid >> 4;
    const int warp = tid >> 5;
    const int lane = tid & 31;
    const int h = blockIdx.y, b = blockIdx.z;
    const int q0 = blockIdx.x * 64;

    const size_t base = (size_t)(b * N_HEADS + h) * SEQ * D_HEAD;
    const float* qp = g_q + base;
    const float* kp = g_k + base;
    const float* vp = g_v + base;

    // load Q tile transposed
    for (int i = tid; i < 64 * 16; i += 256) {
        int r = i >> 4, c4 = (i & 15) << 2;
        float4 q4 = *(const float4*)(qp + (size_t)(q0 + r) * D_HEAD + c4);
        Qt[c4 + 0][r] = q4.x; Qt[c4 + 1][r] = q4.y;
        Qt[c4 + 2][r] = q4.z; Qt[c4 + 3][r] = q4.w;
    }
    if (tid < 64) { m_row[tid] = -1e30f; l_row[tid] = 0.f; }

    float acc[4][4] = {};
    __syncthreads();

    for (int kt = 0; kt < SEQ / 64; kt++) {
        const int k0 = kt * 64;
        // load K transposed + V natural
        for (int i = tid; i < 64 * 16; i += 256) {
            int r = i >> 4, c4 = (i & 15) << 2;
            float4 k4 = *(const float4*)(kp + (size_t)(k0 + r) * D_HEAD + c4);
            Kt[c4 + 0][r] = k4.x; Kt[c4 + 1][r] = k4.y;
            Kt[c4 + 2][r] = k4.z; Kt[c4 + 3][r] = k4.w;
            *(float4*)&Vs[r][c4] = *(const float4*)(vp + (size_t)(k0 + r) * D_HEAD + c4);
        }
        __syncthreads();

        // S = Q @ K^T  (scaled)
        float s[4][4] = {};
#pragma unroll 8
        for (int d = 0; d < 64; d++) {
            float qr[4], kr[4];
#pragma unroll
            for (int i = 0; i < 4; i++) qr[i] = Qt[d][(ty << 2) + i];
#pragma unroll
            for (int j = 0; j < 4; j++) kr[j] = Kt[d][(tx << 2) + j];
#pragma unroll
            for (int i = 0; i < 4; i++)
#pragma unroll
                for (int j = 0; j < 4; j++)
                    s[i][j] = fmaf(qr[i], kr[j], s[i][j]);
        }
        const float scale = 0.125f;   // 1/sqrt(64)
#pragma unroll
        for (int i = 0; i < 4; i++) {
            float4 sv = make_float4(s[i][0] * scale, s[i][1] * scale,
                                    s[i][2] * scale, s[i][3] * scale);
            *(float4*)&Ps[(ty << 2) + i][tx << 2] = sv;
        }
        __syncthreads();

        // online softmax: warp w owns rows [8w, 8w+8)
#pragma unroll
        for (int rr = 0; rr < 8; rr++) {
            int r = (warp << 3) + rr;
            float x0 = Ps[r][lane];
            float x1 = Ps[r][lane + 32];
            float mx = fmaxf(x0, x1);
#pragma unroll
            for (int off = 16; off > 0; off >>= 1)
                mx = fmaxf(mx, __shfl_xor_sync(0xffffffffu, mx, off));
            float m_old = m_row[r];
            float m_new = fmaxf(m_old, mx);
            float p0 = __expf(x0 - m_new);
            float p1 = __expf(x1 - m_new);
            Ps[r][lane] = p0;
            Ps[r][lane + 32] = p1;
            float psum = p0 + p1;
#pragma unroll
            for (int off = 16; off > 0; off >>= 1)
                psum += __shfl_xor_sync(0xffffffffu, psum, off);
            if (lane == 0) {
                float al = __expf(m_old - m_new);
                alpha_s[r] = al;
                l_row[r] = l_row[r] * al + psum;
                m_row[r] = m_new;
            }
        }
        __syncthreads();

        // O = alpha*O + P @ V
#pragma unroll
        for (int i = 0; i < 4; i++) {
            float al = alpha_s[(ty << 2) + i];
#pragma unroll
            for (int j = 0; j < 4; j++) acc[i][j] *= al;
        }
#pragma unroll 8
        for (int kk = 0; kk < 64; kk++) {
            float4 v4 = *(const float4*)&Vs[kk][tx << 2];
            float vv[4] = {v4.x, v4.y, v4.z, v4.w};
            float pv[4];
#pragma unroll
            for (int i = 0; i < 4; i++) pv[i] = Ps[(ty << 2) + i][kk];
#pragma unroll
            for (int i = 0; i < 4; i++)
#pragma unroll
                for (int j = 0; j < 4; j++)
                    acc[i][j] = fmaf(pv[i], vv[j], acc[i][j]);
        }
        __syncthreads();
    }

    // write O/l to g_attn in [B,T,C] layout so out-proj is a plain GEMM
#pragma unroll
    for (int i = 0; i < 4; i++) {
        int r = (ty << 2) + i;
        float linv = 1.0f / l_row[r];
        float4 o = make_float4(acc[i][0] * linv, acc[i][1] * linv,
                               acc[i][2] * linv, acc[i][3] * linv);
        *(float4*)(g_attn + ((size_t)b * SEQ + q0 + r) * D_MODEL
                   + h * D_HEAD + (tx << 2)) = o;
    }
}

// ---------------------------------------------------------------------------
// Launch: x,w_qkv,b_qkv,w_out,b_out -> d_out [B,T,C] float32
// ---------------------------------------------------------------------------
extern "C" void kernel_launch(void* const* d_in, const int* in_sizes, int n_in,
                              void* d_out, int out_size)
{
    const float* x     = (const float*)d_in[0];
    const float* w_qkv = (const float*)d_in[1];
    const float* b_qkv = (const float*)d_in[2];
    const float* w_out = (const float*)d_in[3];
    const float* b_out = (const float*)d_in[4];
    float* out = (float*)d_out;

    // Allow >48KB dynamic smem for the attention kernel (idempotent; not a
    // stream op, so it is graph-capture-safe).
    static bool attr_set = false;
    if (!attr_set) {
        cudaFuncSetAttribute(attn_kernel,
                             cudaFuncAttributeMaxDynamicSharedMemorySize,
                             ATTN_SMEM_BYTES);
        attr_set = true;
    }

    // 1) QKV projection + scatter to [B,H,T,Dh]
    gemm_kernel<<<dim3(3 * D_MODEL / BN, BATCH * SEQ / BM), 256>>>(
        x, w_qkv, b_qkv, nullptr, 3 * D_MODEL, D_MODEL, 1);

    // 2) flash attention -> g_attn [B,T,C]
    attn_kernel<<<dim3(SEQ / 64, N_HEADS, BATCH), 256, ATTN_SMEM_BYTES>>>();

    // 3) output projection -> d_out
    gemm_kernel<<<dim3(D_MODEL / BN, BATCH * SEQ / BM), 256>>>(
        nullptr, w_out, b_out, out, D_MODEL, D_MODEL, 0);
}

// round 3
// speedup vs baseline: 2.0572x; 2.0572x over previous
#include <cuda_runtime.h>
#include <cstdint>

#define D_MODEL 1024
#define N_HEADS 16
#define D_HEAD  64
#define BATCH   4
#define SEQ     2048

// Scratch (allocation-free rule: __device__ globals)
__device__ float g_q[BATCH * N_HEADS * SEQ * D_HEAD];     // [B,H,T,Dh]
__device__ float g_k[BATCH * N_HEADS * SEQ * D_HEAD];
__device__ float g_v[BATCH * N_HEADS * SEQ * D_HEAD];
__device__ float g_attn[BATCH * SEQ * D_MODEL];           // [B,T,C]

// ---------------------------------------------------------------------------
// tf32 helpers
// ---------------------------------------------------------------------------
__device__ __forceinline__ uint32_t f2tf(float x) {
    uint32_t r;
    asm("cvt.rna.tf32.f32 %0, %1;" : "=r"(r) : "f"(x));
    return r;
}

// D += A @ B  (m16n8k8, row.col, tf32 in, f32 acc)
// a0:(g,t) a1:(g+8,t) a2:(g,t+4) a3:(g+8,t+4)   [g=lane>>2, t=lane&3]
// b0:(k=t,n=g) b1:(k=t+4,n=g)
// c0:(g,2t) c1:(g,2t+1) c2:(g+8,2t) c3:(g+8,2t+1)
__device__ __forceinline__ void mma_tf32(float c[4], const uint32_t a[4],
                                         const uint32_t b[2]) {
    asm volatile(
        "mma.sync.aligned.m16n8k8.row.col.f32.tf32.tf32.f32 "
        "{%0,%1,%2,%3}, {%4,%5,%6,%7}, {%8,%9}, {%0,%1,%2,%3};"
        : "+f"(c[0]), "+f"(c[1]), "+f"(c[2]), "+f"(c[3])
        : "r"(a[0]), "r"(a[1]), "r"(a[2]), "r"(a[3]), "r"(b[0]), "r"(b[1]));
}

// ---------------------------------------------------------------------------
// tf32 GEMM: C[M,N] = A[M,K] @ B[K,N] + bias
// BM=BN=128, BK=32, 256 threads = 8 warps (2 m-warps x 4 n-warps),
// warp tile 64x32 = 4 m16 x 4 n8.
// As stride 36 (A-frag reads conflict-free), Bs stride 136 (B-frag reads cf).
// mode 0: A = g_attn, plain store. mode 1: A = x, scatter into g_q/g_k/g_v.
// ---------------------------------------------------------------------------
__global__ __launch_bounds__(256) void gemm_tf32(
    const float* __restrict__ A_ext, const float* __restrict__ B,
    const float* __restrict__ bias, float* __restrict__ C,
    int N, int K, int mode)
{
    __shared__ uint32_t As[128][36];
    __shared__ uint32_t Bs[32][136];

    const float* A = (mode == 1) ? A_ext : g_attn;

    const int tid  = threadIdx.x;
    const int warp = tid >> 5, lane = tid & 31;
    const int g = lane >> 2, t = lane & 3;
    const int wm = warp >> 2;       // 0..1 -> m offset 64*wm
    const int wn = warp & 3;        // 0..3 -> n offset 32*wn
    const int bx = blockIdx.x, by = blockIdx.y;

    const float* Ab = A + (size_t)by * 128 * K;
    const float* Bb = B + (size_t)bx * 128;

    float acc[4][4][4];
#pragma unroll
    for (int mi = 0; mi < 4; mi++)
#pragma unroll
        for (int ni = 0; ni < 4; ni++)
#pragma unroll
            for (int e = 0; e < 4; e++) acc[mi][ni][e] = 0.f;

    for (int k0 = 0; k0 < K; k0 += 32) {
        // stage A tile 128x32 (1024 float4, 4 per thread)
#pragma unroll
        for (int it = 0; it < 4; it++) {
            int idx = tid + it * 256;
            int r = idx >> 3, c4 = (idx & 7) << 2;
            float4 v = *(const float4*)(Ab + (size_t)r * K + k0 + c4);
            As[r][c4 + 0] = f2tf(v.x); As[r][c4 + 1] = f2tf(v.y);
            As[r][c4 + 2] = f2tf(v.z); As[r][c4 + 3] = f2tf(v.w);
        }
        // stage B tile 32x128
#pragma unroll
        for (int it = 0; it < 4; it++) {
            int idx = tid + it * 256;
            int r = idx >> 5, c4 = (idx & 31) << 2;
            float4 v = *(const float4*)(Bb + (size_t)(k0 + r) * N + c4);
            Bs[r][c4 + 0] = f2tf(v.x); Bs[r][c4 + 1] = f2tf(v.y);
            Bs[r][c4 + 2] = f2tf(v.z); Bs[r][c4 + 3] = f2tf(v.w);
        }
        __syncthreads();

#pragma unroll
        for (int kk = 0; kk < 32; kk += 8) {
            uint32_t af[4][4], bf[4][2];
#pragma unroll
            for (int mi = 0; mi < 4; mi++) {
                int m = wm * 64 + mi * 16;
                af[mi][0] = As[m + g][kk + t];
                af[mi][1] = As[m + g + 8][kk + t];
                af[mi][2] = As[m + g][kk + t + 4];
                af[mi][3] = As[m + g + 8][kk + t + 4];
            }
#pragma unroll
            for (int ni = 0; ni < 4; ni++) {
                int n = wn * 32 + ni * 8 + g;
                bf[ni][0] = Bs[kk + t][n];
                bf[ni][1] = Bs[kk + t + 4][n];
            }
#pragma unroll
            for (int mi = 0; mi < 4; mi++)
#pragma unroll
                for (int ni = 0; ni < 4; ni++)
                    mma_tf32(acc[mi][ni], af[mi], bf[ni]);
        }
        __syncthreads();
    }

    // epilogue
#pragma unroll
    for (int mi = 0; mi < 4; mi++) {
        int r0 = by * 128 + wm * 64 + mi * 16 + g;
        int r1 = r0 + 8;
#pragma unroll
        for (int ni = 0; ni < 4; ni++) {
            int c = bx * 128 + wn * 32 + ni * 8 + 2 * t;
            float b0v = bias[c], b1v = bias[c + 1];
            float e00 = acc[mi][ni][0] + b0v, e01 = acc[mi][ni][1] + b1v;
            float e10 = acc[mi][ni][2] + b0v, e11 = acc[mi][ni][3] + b1v;
            if (mode == 0) {
                *(float2*)(C + (size_t)r0 * N + c) = make_float2(e00, e01);
                *(float2*)(C + (size_t)r1 * N + c) = make_float2(e10, e11);
            } else {
#pragma unroll
                for (int e = 0; e < 4; e++) {
                    int r = (e < 2) ? r0 : r1;
                    int cc = c + (e & 1);
                    float val = (e == 0) ? e00 : (e == 1) ? e01 : (e == 2) ? e10 : e11;
                    int b = r >> 11, tt = r & 2047;
                    int s = cc >> 10, rem = cc & 1023;
                    int h = rem >> 6, d = rem & 63;
                    float* dst = (s == 0) ? g_q : (s == 1) ? g_k : g_v;
                    dst[((((size_t)b << 4) + h) * SEQ + tt) * D_HEAD + d] = val;
                }
            }
        }
    }
}

// ---------------------------------------------------------------------------
// Flash attention, tf32 tensor-core. One block = 64-row Q tile of one (b,h).
// 256 threads = 8 warps: wm = warp&3 (m16 band), wn = warp>>2 (32-col half).
// Warp tile 16x32 = 1 m16 x 4 n8, for both S=QK^T and O=PV.
// Dynamic smem (uint32 words):
//   Qs [64][68]  tf32 [qrow][d]
//   Ks [64][68]  tf32 [krow][d]
//   Vs [64][72]  tf32 [krow][d]   (stride 72: PV B-frag reads conflict-free)
//   Ps [64][68]  scores f32 -> probs tf32
// ---------------------------------------------------------------------------
#define QS_OFF 0
#define KS_OFF (64 * 68)
#define VS_OFF (2 * 64 * 68)
#define PS_OFF (2 * 64 * 68 + 64 * 72)
#define ATTN_SMEM_WORDS (3 * 64 * 68 + 64 * 72)
#define ATTN_SMEM_BYTES (ATTN_SMEM_WORDS * 4)

__global__ __launch_bounds__(256) void attn_tf32()
{
    extern __shared__ uint32_t sm[];
    uint32_t* Qs = sm + QS_OFF;
    uint32_t* Ks = sm + KS_OFF;
    uint32_t* Vs = sm + VS_OFF;
    uint32_t* Ps = sm + PS_OFF;
    __shared__ float m_row[64], l_row[64], alpha_s[64];

    const int tid  = threadIdx.x;
    const int warp = tid >> 5, lane = tid & 31;
    const int g = lane >> 2, t = lane & 3;
    const int wm = warp & 3;        // m16 band: rows [16*wm, 16*wm+16)
    const int wn = warp >> 2;       // col half: cols [32*wn, 32*wn+32)
    const int h = blockIdx.y, b = blockIdx.z;
    const int q0 = blockIdx.x * 64;

    const size_t base = (size_t)(b * N_HEADS + h) * SEQ * D_HEAD;
    const float* qp = g_q + base;
    const float* kp = g_k + base;
    const float* vp = g_v + base;

    // load Q tile (64x64), convert to tf32
#pragma unroll
    for (int it = 0; it < 4; it++) {
        int idx = tid + it * 256;
        int r = idx >> 4, c4 = (idx & 15) << 2;
        float4 v = *(const float4*)(qp + (size_t)(q0 + r) * D_HEAD + c4);
        Qs[r * 68 + c4 + 0] = f2tf(v.x); Qs[r * 68 + c4 + 1] = f2tf(v.y);
        Qs[r * 68 + c4 + 2] = f2tf(v.z); Qs[r * 68 + c4 + 3] = f2tf(v.w);
    }
    if (tid < 64) { m_row[tid] = -1e30f; l_row[tid] = 0.f; }

    float oacc[4][4];
#pragma unroll
    for (int ni = 0; ni < 4; ni++)
#pragma unroll
        for (int e = 0; e < 4; e++) oacc[ni][e] = 0.f;

    __syncthreads();

    for (int kt = 0; kt < SEQ / 64; kt++) {
        const int k0 = kt * 64;
        // load K, V tiles
#pragma unroll
        for (int it = 0; it < 4; it++) {
            int idx = tid + it * 256;
            int r = idx >> 4, c4 = (idx & 15) << 2;
            float4 kv = *(const float4*)(kp + (size_t)(k0 + r) * D_HEAD + c4);
            Ks[r * 68 + c4 + 0] = f2tf(kv.x); Ks[r * 68 + c4 + 1] = f2tf(kv.y);
            Ks[r * 68 + c4 + 2] = f2tf(kv.z); Ks[r * 68 + c4 + 3] = f2tf(kv.w);
            float4 vv = *(const float4*)(vp + (size_t)(k0 + r) * D_HEAD + c4);
            Vs[r * 72 + c4 + 0] = f2tf(vv.x); Vs[r * 72 + c4 + 1] = f2tf(vv.y);
            Vs[r * 72 + c4 + 2] = f2tf(vv.z); Vs[r * 72 + c4 + 3] = f2tf(vv.w);
        }
        __syncthreads();

        // S = Q @ K^T : A = Qs[qrow][d], B[k=d][n=kpos] = Ks[kpos][d]
        float sacc[4][4];
#pragma unroll
        for (int ni = 0; ni < 4; ni++)
#pragma unroll
            for (int e = 0; e < 4; e++) sacc[ni][e] = 0.f;

#pragma unroll
        for (int kk = 0; kk < 64; kk += 8) {
            uint32_t af[4], bf[4][2];
            int m = wm * 16;
            af[0] = Qs[(m + g) * 68 + kk + t];
            af[1] = Qs[(m + g + 8) * 68 + kk + t];
            af[2] = Qs[(m + g) * 68 + kk + t + 4];
            af[3] = Qs[(m + g + 8) * 68 + kk + t + 4];
#pragma unroll
            for (int ni = 0; ni < 4; ni++) {
                int n = wn * 32 + ni * 8 + g;       // k position
                bf[ni][0] = Ks[n * 68 + kk + t];
                bf[ni][1] = Ks[n * 68 + kk + t + 4];
            }
#pragma unroll
            for (int ni = 0; ni < 4; ni++)
                mma_tf32(sacc[ni], af, bf[ni]);
        }

        // write scaled scores (f32 bits) to Ps
        const float scale = 0.125f;
#pragma unroll
        for (int ni = 0; ni < 4; ni++) {
            int r0 = wm * 16 + g, r1 = r0 + 8;
            int c = wn * 32 + ni * 8 + 2 * t;
            Ps[r0 * 68 + c]     = __float_as_uint(sacc[ni][0] * scale);
            Ps[r0 * 68 + c + 1] = __float_as_uint(sacc[ni][1] * scale);
            Ps[r1 * 68 + c]     = __float_as_uint(sacc[ni][2] * scale);
            Ps[r1 * 68 + c + 1] = __float_as_uint(sacc[ni][3] * scale);
        }
        __syncthreads();

        // online softmax: warp w owns rows [8w, 8w+8); probs stored as tf32
#pragma unroll
        for (int rr = 0; rr < 8; rr++) {
            int r = (warp << 3) + rr;
            float x0 = __uint_as_float(Ps[r * 68 + lane]);
            float x1 = __uint_as_float(Ps[r * 68 + lane + 32]);
            float mx = fmaxf(x0, x1);
#pragma unroll
            for (int off = 16; off > 0; off >>= 1)
                mx = fmaxf(mx, __shfl_xor_sync(0xffffffffu, mx, off));
            float m_old = m_row[r];
            float m_new = fmaxf(m_old, mx);
            float p0 = __expf(x0 - m_new);
            float p1 = __expf(x1 - m_new);
            Ps[r * 68 + lane]      = f2tf(p0);
            Ps[r * 68 + lane + 32] = f2tf(p1);
            float psum = p0 + p1;
#pragma unroll
            for (int off = 16; off > 0; off >>= 1)
                psum += __shfl_xor_sync(0xffffffffu, psum, off);
            if (lane == 0) {
                float al = __expf(m_old - m_new);
                alpha_s[r] = al;
                l_row[r] = l_row[r] * al + psum;
                m_row[r] = m_new;
            }
        }
        __syncthreads();

        // O = alpha*O + P @ V : A = Ps[qrow][kpos], B[k=kpos][n=d] = Vs[kpos][d]
        {
            int r0 = wm * 16 + g, r1 = r0 + 8;
            float a0 = alpha_s[r0], a1 = alpha_s[r1];
#pragma unroll
            for (int ni = 0; ni < 4; ni++) {
                oacc[ni][0] *= a0; oacc[ni][1] *= a0;
                oacc[ni][2] *= a1; oacc[ni][3] *= a1;
            }
        }
#pragma unroll
        for (int kk = 0; kk < 64; kk += 8) {
            uint32_t af[4], bf[4][2];
            int m = wm * 16;
            af[0] = Ps[(m + g) * 68 + kk + t];
            af[1] = Ps[(m + g + 8) * 68 + kk + t];
            af[2] = Ps[(m + g) * 68 + kk + t + 4];
            af[3] = Ps[(m + g + 8) * 68 + kk + t + 4];
#pragma unroll
            for (int ni = 0; ni < 4; ni++) {
                int n = wn * 32 + ni * 8 + g;       // d column
                bf[ni][0] = Vs[(kk + t) * 72 + n];
                bf[ni][1] = Vs[(kk + t + 4) * 72 + n];
            }
#pragma unroll
            for (int ni = 0; ni < 4; ni++)
                mma_tf32(oacc[ni], af, bf[ni]);
        }
        __syncthreads();
    }

    // normalize and write to g_attn [B,T,C]
    {
        int r0 = wm * 16 + g, r1 = r0 + 8;
        float li0 = 1.0f / l_row[r0], li1 = 1.0f / l_row[r1];
#pragma unroll
        for (int ni = 0; ni < 4; ni++) {
            int c = wn * 32 + ni * 8 + 2 * t;       // d column
            float* dst0 = g_attn + ((size_t)b * SEQ + q0 + r0) * D_MODEL + h * D_HEAD + c;
            float* dst1 = g_attn + ((size_t)b * SEQ + q0 + r1) * D_MODEL + h * D_HEAD + c;
            *(float2*)dst0 = make_float2(oacc[ni][0] * li0, oacc[ni][1] * li0);
            *(float2*)dst1 = make_float2(oacc[ni][2] * li1, oacc[ni][3] * li1);
        }
    }
}

// ---------------------------------------------------------------------------
// Launch
// ---------------------------------------------------------------------------
extern "C" void kernel_launch(void* const* d_in, const int* in_sizes, int n_in,
                              void* d_out, int out_size)
{
    const float* x     = (const float*)d_in[0];
    const float* w_qkv = (const float*)d_in[1];
    const float* b_qkv = (const float*)d_in[2];
    const float* w_out = (const float*)d_in[3];
    const float* b_out = (const float*)d_in[4];
    float* out = (float*)d_out;

    static bool attr_set = false;
    if (!attr_set) {
        cudaFuncSetAttribute(attn_tf32,
                             cudaFuncAttributeMaxDynamicSharedMemorySize,
                             ATTN_SMEM_BYTES);
        attr_set = true;
    }

    // 1) QKV projection + scatter to [B,H,T,Dh]
    gemm_tf32<<<dim3(3 * D_MODEL / 128, BATCH * SEQ / 128), 256>>>(
        x, w_qkv, b_qkv, nullptr, 3 * D_MODEL, D_MODEL, 1);

    // 2) flash attention (tensor core) -> g_attn [B,T,C]
    attn_tf32<<<dim3(SEQ / 64, N_HEADS, BATCH), 256, ATTN_SMEM_BYTES>>>();

    // 3) output projection -> d_out
    gemm_tf32<<<dim3(D_MODEL / 128, BATCH * SEQ / 128), 256>>>(
        nullptr, w_out, b_out, out, D_MODEL, D_MODEL, 0);
}

// round 5
// speedup vs baseline: 3.2759x; 1.5924x over previous
#include <cuda_runtime.h>
#include <cstdint>

#define D_MODEL 1024
#define N_HEADS 16
#define D_HEAD  64
#define BATCH   4
#define SEQ     2048

// Scratch (allocation-free rule: __device__ globals)
__device__ float g_q[BATCH * N_HEADS * SEQ * D_HEAD];     // [B,H,T,Dh]
__device__ float g_k[BATCH * N_HEADS * SEQ * D_HEAD];
__device__ float g_v[BATCH * N_HEADS * SEQ * D_HEAD];
__device__ float g_attn[BATCH * SEQ * D_MODEL];           // [B,T,C]

// ---------------------------------------------------------------------------
// helpers
// ---------------------------------------------------------------------------
__device__ __forceinline__ uint32_t smem_u32(const void* p) {
    return (uint32_t)__cvta_generic_to_shared(p);
}
__device__ __forceinline__ void cp_async16(uint32_t dst, const void* src) {
    asm volatile("cp.async.cg.shared.global [%0], [%1], 16;" :: "r"(dst), "l"(src));
}
#define CP_COMMIT() asm volatile("cp.async.commit_group;")
#define CP_WAIT(n)  asm volatile("cp.async.wait_group %0;" :: "n"(n))

__device__ __forceinline__ uint32_t f2tf(float x) {
    uint32_t r;
    asm("cvt.rna.tf32.f32 %0, %1;" : "=r"(r) : "f"(x));
    return r;
}
// convert 4 packed fp32 words in smem to tf32 (RNA), in place
__device__ __forceinline__ void cvt4_inplace(uint32_t* p) {
    uint4 v = *(uint4*)p;
    v.x = f2tf(__uint_as_float(v.x));
    v.y = f2tf(__uint_as_float(v.y));
    v.z = f2tf(__uint_as_float(v.z));
    v.w = f2tf(__uint_as_float(v.w));
    *(uint4*)p = v;
}

// D += A @ B  (m16n8k8, row.col, tf32 in, f32 acc)
// a0:(g,t) a1:(g+8,t) a2:(g,t+4) a3:(g+8,t+4)   [g=lane>>2, t=lane&3]
// b0:(k=t,n=g) b1:(k=t+4,n=g)
// c0:(g,2t) c1:(g,2t+1) c2:(g+8,2t) c3:(g+8,2t+1)
__device__ __forceinline__ void mma_tf32(float c[4], const uint32_t a[4],
                                         const uint32_t b[2]) {
    asm volatile(
        "mma.sync.aligned.m16n8k8.row.col.f32.tf32.tf32.f32 "
        "{%0,%1,%2,%3}, {%4,%5,%6,%7}, {%8,%9}, {%0,%1,%2,%3};"
        : "+f"(c[0]), "+f"(c[1]), "+f"(c[2]), "+f"(c[3])
        : "r"(a[0]), "r"(a[1]), "r"(a[2]), "r"(a[3]), "r"(b[0]), "r"(b[1]));
}

// ---------------------------------------------------------------------------
// tf32 GEMM: C[M,N] = A[M,K] @ B[K,N] + bias
// BM=BN=128, BK=32, 256 threads = 8 warps (2 m x 4 n), warp tile 64x32.
// cp.async 2-stage double buffer; after wait, each thread RNA-converts the
// words it copied (in place, pre-barrier -> no extra sync).
// ---------------------------------------------------------------------------
#define GA_WORDS (128 * 36)
#define GB_WORDS (32 * 136)
#define G_STAGE  (GA_WORDS + GB_WORDS)
#define GEMM_SMEM_BYTES (2 * G_STAGE * 4)

__global__ __launch_bounds__(256, 2) void gemm_tf32(
    const float* __restrict__ A_ext, const float* __restrict__ B,
    const float* __restrict__ bias, float* __restrict__ C,
    int N, int K, int mode)
{
    extern __shared__ float smg[];
    const float* A = (mode == 1) ? A_ext : g_attn;

    const int tid  = threadIdx.x;
    const int warp = tid >> 5, lane = tid & 31;
    const int g = lane >> 2, t = lane & 3;
    const int wm = warp >> 2;       // 0..1 -> m offset 64*wm
    const int wn = warp & 3;        // 0..3 -> n offset 32*wn
    const int bx = blockIdx.x, by = blockIdx.y;

    const float* Ab = A + (size_t)by * 128 * K;
    const float* Bb = B + (size_t)bx * 128;
    const uint32_t smb = smem_u32(smg);

    // load mappings (per-thread, 4 16B chunks each for A and B)
    const int ar = tid >> 3, ac = (tid & 7) << 2;        // A: 128 rows x 32
    const int br = tid >> 5, bc = (tid & 31) << 2;       // B: 32 rows x 128

    float acc[4][4][4];
#pragma unroll
    for (int mi = 0; mi < 4; mi++)
#pragma unroll
        for (int ni = 0; ni < 4; ni++)
#pragma unroll
            for (int e = 0; e < 4; e++) acc[mi][ni][e] = 0.f;

    // prologue: stage 0
    {
        uint32_t ab = smb, bb = smb + GA_WORDS * 4;
#pragma unroll
        for (int it = 0; it < 4; it++) {
            int r = ar + it * 32;
            cp_async16(ab + (r * 36 + ac) * 4, Ab + (size_t)r * K + ac);
        }
#pragma unroll
        for (int it = 0; it < 4; it++) {
            int r = br + it * 8;
            cp_async16(bb + (r * 136 + bc) * 4, Bb + (size_t)r * N + bc);
        }
        CP_COMMIT();
    }

    for (int k0 = 0, s = 0; k0 < K; k0 += 32, s ^= 1) {
        if (k0 + 32 < K) {
            uint32_t ab = smb + (s ^ 1) * G_STAGE * 4, bb = ab + GA_WORDS * 4;
#pragma unroll
            for (int it = 0; it < 4; it++) {
                int r = ar + it * 32;
                cp_async16(ab + (r * 36 + ac) * 4, Ab + (size_t)r * K + k0 + 32 + ac);
            }
#pragma unroll
            for (int it = 0; it < 4; it++) {
                int r = br + it * 8;
                cp_async16(bb + (r * 136 + bc) * 4, Bb + (size_t)(k0 + 32 + r) * N + bc);
            }
            CP_COMMIT();
            CP_WAIT(1);
        } else {
            CP_WAIT(0);
        }

        // RNA-convert this thread's own copied words (visible post-wait),
        // then the barrier publishes them.
        {
            uint32_t* As = (uint32_t*)smg + s * G_STAGE;
            uint32_t* Bs = As + GA_WORDS;
#pragma unroll
            for (int it = 0; it < 4; it++)
                cvt4_inplace(&As[(ar + it * 32) * 36 + ac]);
#pragma unroll
            for (int it = 0; it < 4; it++)
                cvt4_inplace(&Bs[(br + it * 8) * 136 + bc]);
        }
        __syncthreads();

        const uint32_t* As = (const uint32_t*)smg + s * G_STAGE;
        const uint32_t* Bs = As + GA_WORDS;

#pragma unroll
        for (int kk = 0; kk < 32; kk += 8) {
            uint32_t af[4][4], bf[4][2];
#pragma unroll
            for (int mi = 0; mi < 4; mi++) {
                int m = wm * 64 + mi * 16;
                af[mi][0] = As[(m + g) * 36 + kk + t];
                af[mi][1] = As[(m + g + 8) * 36 + kk + t];
                af[mi][2] = As[(m + g) * 36 + kk + t + 4];
                af[mi][3] = As[(m + g + 8) * 36 + kk + t + 4];
            }
#pragma unroll
            for (int ni = 0; ni < 4; ni++) {
                int n = wn * 32 + ni * 8 + g;
                bf[ni][0] = Bs[(kk + t) * 136 + n];
                bf[ni][1] = Bs[(kk + t + 4) * 136 + n];
            }
#pragma unroll
            for (int mi = 0; mi < 4; mi++)
#pragma unroll
                for (int ni = 0; ni < 4; ni++)
                    mma_tf32(acc[mi][ni], af[mi], bf[ni]);
        }
        __syncthreads();
    }

    // epilogue
#pragma unroll
    for (int mi = 0; mi < 4; mi++) {
        int r0 = by * 128 + wm * 64 + mi * 16 + g;
        int r1 = r0 + 8;
#pragma unroll
        for (int ni = 0; ni < 4; ni++) {
            int c = bx * 128 + wn * 32 + ni * 8 + 2 * t;
            float b0v = bias[c], b1v = bias[c + 1];
            float e00 = acc[mi][ni][0] + b0v, e01 = acc[mi][ni][1] + b1v;
            float e10 = acc[mi][ni][2] + b0v, e11 = acc[mi][ni][3] + b1v;
            if (mode == 0) {
                *(float2*)(C + (size_t)r0 * N + c) = make_float2(e00, e01);
                *(float2*)(C + (size_t)r1 * N + c) = make_float2(e10, e11);
            } else {
#pragma unroll
                for (int e = 0; e < 4; e++) {
                    int r = (e < 2) ? r0 : r1;
                    int cc = c + (e & 1);
                    float val = (e == 0) ? e00 : (e == 1) ? e01 : (e == 2) ? e10 : e11;
                    int b = r >> 11, tt = r & 2047;
                    int sidx = cc >> 10, rem = cc & 1023;
                    int h = rem >> 6, d = rem & 63;
                    float* dst = (sidx == 0) ? g_q : (sidx == 1) ? g_k : g_v;
                    dst[((((size_t)b << 4) + h) * SEQ + tt) * D_HEAD + d] = val;
                }
            }
        }
    }
}

// ---------------------------------------------------------------------------
// Flash attention v2, tf32 tensor core, register-resident softmax.
// Block = 128 q-rows of one (b,h); 8 warps, each owns 16 rows.
// Q frags in registers; K/V double-buffered cp.async with in-place RNA
// convert; P remapped C-frag -> A-frag via shuffles, f2tf'd.
// ---------------------------------------------------------------------------
#define KSTR 68
#define VSTR 72
#define KV_STAGE (64 * KSTR + 64 * VSTR)       // 8960 words
#define ATTN_SMEM_BYTES (2 * KV_STAGE * 4)     // 71680 B

__global__ __launch_bounds__(256, 2) void attn_tf32()
{
    extern __shared__ float sma[];
    const int tid  = threadIdx.x;
    const int warp = tid >> 5, lane = tid & 31;
    const int g = lane >> 2, t = lane & 3;
    const int h = blockIdx.y, b = blockIdx.z;
    const int q0 = blockIdx.x * 128;
    const int qb = warp * 16;

    const size_t base = (size_t)(b * N_HEADS + h) * SEQ * D_HEAD;
    const float* qp = g_q + base + (size_t)q0 * D_HEAD;
    const float* kp = g_k + base;
    const float* vp = g_v + base;
    const uint32_t smb = smem_u32(sma);

    // ---- stage Q (128x64) into sma with stride 68, convert, frags to regs
#pragma unroll
    for (int it = 0; it < 8; it++) {
        int idx = tid + it * 256;
        int r = idx >> 4, c4 = (idx & 15) << 2;
        cp_async16(smb + (r * 68 + c4) * 4, qp + (size_t)r * 64 + c4);
    }
    CP_COMMIT();
    CP_WAIT(0);
    {
        uint32_t* Qw = (uint32_t*)sma;
#pragma unroll
        for (int it = 0; it < 8; it++) {
            int idx = tid + it * 256;
            int r = idx >> 4, c4 = (idx & 15) << 2;
            cvt4_inplace(&Qw[r * 68 + c4]);
        }
    }
    __syncthreads();

    uint32_t qf[8][4];
    {
        const uint32_t* Qs = (const uint32_t*)sma;
#pragma unroll
        for (int j = 0; j < 8; j++) {
            qf[j][0] = Qs[(qb + g) * 68 + 8 * j + t];
            qf[j][1] = Qs[(qb + g + 8) * 68 + 8 * j + t];
            qf[j][2] = Qs[(qb + g) * 68 + 8 * j + t + 4];
            qf[j][3] = Qs[(qb + g + 8) * 68 + 8 * j + t + 4];
        }
    }
    __syncthreads();   // Q reads done; region becomes KV stage 0

    float oacc[8][4];
#pragma unroll
    for (int ni = 0; ni < 8; ni++)
#pragma unroll
        for (int e = 0; e < 4; e++) oacc[ni][e] = 0.f;
    float m0 = -1e30f, m1 = -1e30f, l0 = 0.f, l1 = 0.f;

    // KV load mapping: 64 rows x 64 floats, 4 chunks/thread each of K and V
    const int kr = tid >> 4, kc = (tid & 15) << 2;

    // prologue tile 0
    {
        uint32_t kb = smb, vb = smb + 64 * KSTR * 4;
#pragma unroll
        for (int it = 0; it < 4; it++) {
            int r = kr + it * 16;
            cp_async16(kb + (r * KSTR + kc) * 4, kp + (size_t)r * 64 + kc);
            cp_async16(vb + (r * VSTR + kc) * 4, vp + (size_t)r * 64 + kc);
        }
        CP_COMMIT();
    }

    const float scale = 0.125f;   // 1/sqrt(64)

    for (int kt = 0, s = 0; kt < SEQ / 64; kt++, s ^= 1) {
        if (kt + 1 < SEQ / 64) {
            int k0n = (kt + 1) * 64;
            uint32_t kb = smb + (s ^ 1) * KV_STAGE * 4;
            uint32_t vb = kb + 64 * KSTR * 4;
#pragma unroll
            for (int it = 0; it < 4; it++) {
                int r = kr + it * 16;
                cp_async16(kb + (r * KSTR + kc) * 4, kp + (size_t)(k0n + r) * 64 + kc);
                cp_async16(vb + (r * VSTR + kc) * 4, vp + (size_t)(k0n + r) * 64 + kc);
            }
            CP_COMMIT();
            CP_WAIT(1);
        } else {
            CP_WAIT(0);
        }

        // RNA-convert this thread's own copied K/V words
        {
            uint32_t* Kw = (uint32_t*)sma + s * KV_STAGE;
            uint32_t* Vw = Kw + 64 * KSTR;
#pragma unroll
            for (int it = 0; it < 4; it++) {
                int r = kr + it * 16;
                cvt4_inplace(&Kw[r * KSTR + kc]);
                cvt4_inplace(&Vw[r * VSTR + kc]);
            }
        }
        __syncthreads();

        const uint32_t* Ks = (const uint32_t*)sma + s * KV_STAGE;
        const uint32_t* Vs = Ks + 64 * KSTR;

        // ---- S = Q @ K^T (64 MMAs)
        float sacc[8][4];
#pragma unroll
        for (int ni = 0; ni < 8; ni++)
#pragma unroll
            for (int e = 0; e < 4; e++) sacc[ni][e] = 0.f;

#pragma unroll
        for (int j = 0; j < 8; j++) {
#pragma unroll
            for (int ni = 0; ni < 8; ni++) {
                uint32_t bf[2];
                int n = ni * 8 + g;
                bf[0] = Ks[n * KSTR + 8 * j + t];
                bf[1] = Ks[n * KSTR + 8 * j + t + 4];
                mma_tf32(sacc[ni], qf[j], bf);
            }
        }

        // ---- online softmax in registers (rows g and g+8 of warp band)
        float mx0 = -1e30f, mx1 = -1e30f;
#pragma unroll
        for (int ni = 0; ni < 8; ni++) {
            mx0 = fmaxf(mx0, fmaxf(sacc[ni][0], sacc[ni][1]));
            mx1 = fmaxf(mx1, fmaxf(sacc[ni][2], sacc[ni][3]));
        }
        mx0 = fmaxf(mx0, __shfl_xor_sync(0xffffffffu, mx0, 1));
        mx0 = fmaxf(mx0, __shfl_xor_sync(0xffffffffu, mx0, 2));
        mx1 = fmaxf(mx1, __shfl_xor_sync(0xffffffffu, mx1, 1));
        mx1 = fmaxf(mx1, __shfl_xor_sync(0xffffffffu, mx1, 2));

        float mn0 = fmaxf(m0, mx0 * scale), mn1 = fmaxf(m1, mx1 * scale);
        float a0 = __expf(m0 - mn0), a1 = __expf(m1 - mn1);
        float rs0 = 0.f, rs1 = 0.f;
#pragma unroll
        for (int ni = 0; ni < 8; ni++) {
            sacc[ni][0] = __expf(fmaf(sacc[ni][0], scale, -mn0));
            sacc[ni][1] = __expf(fmaf(sacc[ni][1], scale, -mn0));
            sacc[ni][2] = __expf(fmaf(sacc[ni][2], scale, -mn1));
            sacc[ni][3] = __expf(fmaf(sacc[ni][3], scale, -mn1));
            rs0 += sacc[ni][0] + sacc[ni][1];
            rs1 += sacc[ni][2] + sacc[ni][3];
        }
        rs0 += __shfl_xor_sync(0xffffffffu, rs0, 1);
        rs0 += __shfl_xor_sync(0xffffffffu, rs0, 2);
        rs1 += __shfl_xor_sync(0xffffffffu, rs1, 1);
        rs1 += __shfl_xor_sync(0xffffffffu, rs1, 2);
        l0 = l0 * a0 + rs0; l1 = l1 * a1 + rs1;
        m0 = mn0; m1 = mn1;
#pragma unroll
        for (int ni = 0; ni < 8; ni++) {
            oacc[ni][0] *= a0; oacc[ni][1] *= a0;
            oacc[ni][2] *= a1; oacc[ni][3] *= a1;
        }

        // ---- O += P @ V : remap P C-frags -> A-frags via shuffles (64 MMAs)
        const int srcA = (g << 2) + (t >> 1);   // lane holding cols {t&~1, t|1}
        const int srcB = srcA + 2;              // lane holding cols {t+4 pair}
#pragma unroll
        for (int kj = 0; kj < 8; kj++) {
            float e00 = __shfl_sync(0xffffffffu, sacc[kj][0], srcA);
            float e01 = __shfl_sync(0xffffffffu, sacc[kj][1], srcA);
            float f00 = __shfl_sync(0xffffffffu, sacc[kj][2], srcA);
            float f01 = __shfl_sync(0xffffffffu, sacc[kj][3], srcA);
            float e10 = __shfl_sync(0xffffffffu, sacc[kj][0], srcB);
            float e11 = __shfl_sync(0xffffffffu, sacc[kj][1], srcB);
            float f10 = __shfl_sync(0xffffffffu, sacc[kj][2], srcB);
            float f11 = __shfl_sync(0xffffffffu, sacc[kj][3], srcB);
            uint32_t pf[4];
            pf[0] = f2tf((t & 1) ? e01 : e00);   // (g,    t)
            pf[1] = f2tf((t & 1) ? f01 : f00);   // (g+8,  t)
            pf[2] = f2tf((t & 1) ? e11 : e10);   // (g,    t+4)
            pf[3] = f2tf((t & 1) ? f11 : f10);   // (g+8,  t+4)
#pragma unroll
            for (int ni = 0; ni < 8; ni++) {
                uint32_t bf[2];
                int n = ni * 8 + g;
                bf[0] = Vs[(kj * 8 + t) * VSTR + n];
                bf[1] = Vs[(kj * 8 + t + 4) * VSTR + n];
                mma_tf32(oacc[ni], pf, bf);
            }
        }
        __syncthreads();
    }

    // ---- normalize and write to g_attn [B,T,C]
    {
        float li0 = 1.0f / l0, li1 = 1.0f / l1;
        int r0 = q0 + qb + g, r1 = r0 + 8;
#pragma unroll
        for (int ni = 0; ni < 8; ni++) {
            int c = ni * 8 + 2 * t;
            float* d0 = g_attn + ((size_t)b * SEQ + r0) * D_MODEL + h * D_HEAD + c;
            float* d1 = g_attn + ((size_t)b * SEQ + r1) * D_MODEL + h * D_HEAD + c;
            *(float2*)d0 = make_float2(oacc[ni][0] * li0, oacc[ni][1] * li0);
            *(float2*)d1 = make_float2(oacc[ni][2] * li1, oacc[ni][3] * li1);
        }
    }
}

// ---------------------------------------------------------------------------
// Launch
// ---------------------------------------------------------------------------
extern "C" void kernel_launch(void* const* d_in, const int* in_sizes, int n_in,
                              void* d_out, int out_size)
{
    const float* x     = (const float*)d_in[0];
    const float* w_qkv = (const float*)d_in[1];
    const float* b_qkv = (const float*)d_in[2];
    const float* w_out = (const float*)d_in[3];
    const float* b_out = (const float*)d_in[4];
    float* out = (float*)d_out;

    static bool attr_set = false;
    if (!attr_set) {
        cudaFuncSetAttribute(attn_tf32,
                             cudaFuncAttributeMaxDynamicSharedMemorySize,
                             ATTN_SMEM_BYTES);
        cudaFuncSetAttribute(gemm_tf32,
                             cudaFuncAttributeMaxDynamicSharedMemorySize,
                             GEMM_SMEM_BYTES);
        attr_set = true;
    }

    // 1) QKV projection + scatter to [B,H,T,Dh]
    gemm_tf32<<<dim3(3 * D_MODEL / 128, BATCH * SEQ / 128), 256, GEMM_SMEM_BYTES>>>(
        x, w_qkv, b_qkv, nullptr, 3 * D_MODEL, D_MODEL, 1);

    // 2) flash attention (tensor core, register softmax) -> g_attn [B,T,C]
    attn_tf32<<<dim3(SEQ / 128, N_HEADS, BATCH), 256, ATTN_SMEM_BYTES>>>();

    // 3) output projection -> d_out
    gemm_tf32<<<dim3(D_MODEL / 128, BATCH * SEQ / 128), 256, GEMM_SMEM_BYTES>>>(
        nullptr, w_out, b_out, out, D_MODEL, D_MODEL, 0);
}

// round 6
// speedup vs baseline: 7.4005x; 2.2591x over previous
#include <cuda_runtime.h>
#include <cuda_fp16.h>
#include <cstdint>

#define D_MODEL 1024
#define N_HEADS 16
#define D_HEAD  64
#define BATCH   4
#define SEQ     2048

// Scratch (allocation-free rule: __device__ globals), fp16 working set
__device__ __align__(16) __half g_xh[BATCH * SEQ * D_MODEL];
__device__ __align__(16) __half g_wqkvh[D_MODEL * 3 * D_MODEL];
__device__ __align__(16) __half g_wouth[D_MODEL * D_MODEL];
__device__ __align__(16) __half g_qh[BATCH * N_HEADS * SEQ * D_HEAD];
__device__ __align__(16) __half g_kh[BATCH * N_HEADS * SEQ * D_HEAD];
__device__ __align__(16) __half g_vh[BATCH * N_HEADS * SEQ * D_HEAD];
__device__ __align__(16) __half g_attnh[BATCH * SEQ * D_MODEL];

// ---------------------------------------------------------------------------
// helpers
// ---------------------------------------------------------------------------
__device__ __forceinline__ uint32_t smem_u32(const void* p) {
    return (uint32_t)__cvta_generic_to_shared(p);
}
__device__ __forceinline__ void cp_async16(uint32_t dst, const void* src) {
    asm volatile("cp.async.cg.shared.global [%0], [%1], 16;" :: "r"(dst), "l"(src));
}
#define CP_COMMIT() asm volatile("cp.async.commit_group;")
#define CP_WAIT(n)  asm volatile("cp.async.wait_group %0;" :: "n"(n))

__device__ __forceinline__ uint32_t pack_h2(float a, float b) {
    __half2 h = __floats2half2_rn(a, b);
    return *(uint32_t*)&h;
}
__device__ __forceinline__ void ldsm_x4(uint32_t& r0, uint32_t& r1,
                                        uint32_t& r2, uint32_t& r3, uint32_t a) {
    asm volatile("ldmatrix.sync.aligned.m8n8.x4.shared.b16 {%0,%1,%2,%3}, [%4];"
                 : "=r"(r0), "=r"(r1), "=r"(r2), "=r"(r3) : "r"(a));
}
__device__ __forceinline__ void ldsm_x4_t(uint32_t& r0, uint32_t& r1,
                                          uint32_t& r2, uint32_t& r3, uint32_t a) {
    asm volatile("ldmatrix.sync.aligned.m8n8.x4.trans.shared.b16 {%0,%1,%2,%3}, [%4];"
                 : "=r"(r0), "=r"(r1), "=r"(r2), "=r"(r3) : "r"(a));
}

// D += A @ B  (m16n8k16, row.col, f16 in, f32 acc)
// A frag: a0:(g,2t|2t+1) a1:(g+8,..) a2:(g,2t+8..) a3:(g+8,2t+8..)
// B frag: b0:(k=2t..2t+1, n=g) b1:(k=2t+8.., n=g)
// C frag: c0:(g,2t) c1:(g,2t+1) c2:(g+8,2t) c3:(g+8,2t+1)
__device__ __forceinline__ void mma_f16(float c[4], const uint32_t a[4],
                                        const uint32_t b[2]) {
    asm volatile(
        "mma.sync.aligned.m16n8k16.row.col.f32.f16.f16.f32 "
        "{%0,%1,%2,%3}, {%4,%5,%6,%7}, {%8,%9}, {%0,%1,%2,%3};"
        : "+f"(c[0]), "+f"(c[1]), "+f"(c[2]), "+f"(c[3])
        : "r"(a[0]), "r"(a[1]), "r"(a[2]), "r"(a[3]), "r"(b[0]), "r"(b[1]));
}

// ---------------------------------------------------------------------------
// f32 -> f16 convert pre-pass (vectorized). which: 0=x, 1=w_qkv, 2=w_out
// ---------------------------------------------------------------------------
__global__ void f2h_kernel(const float4* __restrict__ src, int which, int n4)
{
    int i = blockIdx.x * blockDim.x + threadIdx.x;
    if (i >= n4) return;
    uint2* dst = (which == 0) ? (uint2*)g_xh
               : (which == 1) ? (uint2*)g_wqkvh : (uint2*)g_wouth;
    float4 v = src[i];
    uint2 o;
    o.x = pack_h2(v.x, v.y);
    o.y = pack_h2(v.z, v.w);
    dst[i] = o;
}

// ---------------------------------------------------------------------------
// fp16 GEMM: C[M,N] = A[M,K] @ B[K,N] + bias (fp32 bias/acc)
// BM=BN=128, BK=32, 256 threads = 8 warps (2 m x 4 n), warp tile 64x32.
// cp.async double buffer of half data; ldmatrix fragment staging.
// As: [128][40] halves (80B rows), Bs: [32][136] halves (272B rows).
// mode 1: A=g_xh, scatter half to g_qh/g_kh/g_vh. mode 0: A=g_attnh, f32 out.
// ---------------------------------------------------------------------------
#define ASTR 40
#define BSTR 136
#define A_BYTES (128 * ASTR * 2)     // 10240
#define B_BYTES (32 * BSTR * 2)      // 8704
#define STG_BYTES (A_BYTES + B_BYTES)
#define GEMM_SMEM_BYTES (2 * STG_BYTES)

__global__ __launch_bounds__(256, 2) void gemm_f16(
    const float* __restrict__ bias, float* __restrict__ Cout,
    int N, int K, int mode)
{
    extern __shared__ __half smg[];
    const __half* A = (mode == 1) ? g_xh : g_attnh;
    const __half* B = (mode == 1) ? g_wqkvh : g_wouth;

    const int tid  = threadIdx.x;
    const int warp = tid >> 5, lane = tid & 31;
    const int g = lane >> 2, t = lane & 3;
    const int wm = warp >> 2;       // 0..1 -> m offset 64*wm
    const int wn = warp & 3;        // 0..3 -> n offset 32*wn
    const int bx = blockIdx.x, by = blockIdx.y;

    const __half* Ab = A + (size_t)by * 128 * K;
    const __half* Bb = B + (size_t)bx * 128;
    const uint32_t smb = smem_u32(smg);

    // cp.async mappings (2 chunks of 16B per thread for each of A and B)
    // A: 128 rows x 32 halves (4 chunks/row); B: 32 rows x 128 halves (16/row)
    // ldmatrix lane mapping
    const int lr = (lane & 7) + ((lane >> 3) & 1) * 8;  // row-in-16
    const int lk = ((lane >> 4) & 1) * 8;               // half-col 0/8

    float acc[4][4][4];
#pragma unroll
    for (int mi = 0; mi < 4; mi++)
#pragma unroll
        for (int ni = 0; ni < 4; ni++)
#pragma unroll
            for (int e = 0; e < 4; e++) acc[mi][ni][e] = 0.f;

    // prologue: stage 0
    {
        uint32_t ab = smb, bb = smb + A_BYTES;
#pragma unroll
        for (int it = 0; it < 2; it++) {
            int c = tid + it * 256;
            int r = c >> 2, cl = (c & 3) * 8;
            cp_async16(ab + (r * ASTR + cl) * 2, Ab + (size_t)r * K + cl);
        }
#pragma unroll
        for (int it = 0; it < 2; it++) {
            int c = tid + it * 256;
            int r = c >> 4, cl = (c & 15) * 8;
            cp_async16(bb + (r * BSTR + cl) * 2, Bb + (size_t)r * N + cl);
        }
        CP_COMMIT();
    }

    for (int k0 = 0, s = 0; k0 < K; k0 += 32, s ^= 1) {
        if (k0 + 32 < K) {
            uint32_t ab = smb + (s ^ 1) * STG_BYTES, bb = ab + A_BYTES;
#pragma unroll
            for (int it = 0; it < 2; it++) {
                int c = tid + it * 256;
                int r = c >> 2, cl = (c & 3) * 8;
                cp_async16(ab + (r * ASTR + cl) * 2, Ab + (size_t)r * K + k0 + 32 + cl);
            }
#pragma unroll
            for (int it = 0; it < 2; it++) {
                int c = tid + it * 256;
                int r = c >> 4, cl = (c & 15) * 8;
                cp_async16(bb + (r * BSTR + cl) * 2, Bb + (size_t)(k0 + 32 + r) * N + cl);
            }
            CP_COMMIT();
            CP_WAIT(1);
        } else {
            CP_WAIT(0);
        }
        __syncthreads();

        const uint32_t aBase = smb + s * STG_BYTES;
        const uint32_t bBase = aBase + A_BYTES;

#pragma unroll
        for (int kk = 0; kk < 2; kk++) {
            uint32_t af[4][4];
#pragma unroll
            for (int mi = 0; mi < 4; mi++) {
                uint32_t addr = aBase +
                    ((wm * 64 + mi * 16 + lr) * ASTR + kk * 16 + lk) * 2;
                ldsm_x4(af[mi][0], af[mi][1], af[mi][2], af[mi][3], addr);
            }
            uint32_t bf[2][4];
#pragma unroll
            for (int ngi = 0; ngi < 2; ngi++) {
                uint32_t addr = bBase +
                    ((kk * 16 + lr) * BSTR + wn * 32 + ngi * 16 + lk) * 2;
                ldsm_x4_t(bf[ngi][0], bf[ngi][1], bf[ngi][2], bf[ngi][3], addr);
            }
#pragma unroll
            for (int mi = 0; mi < 4; mi++)
#pragma unroll
                for (int ni = 0; ni < 4; ni++) {
                    uint32_t b2[2] = { bf[ni >> 1][(ni & 1) * 2],
                                       bf[ni >> 1][(ni & 1) * 2 + 1] };
                    mma_f16(acc[mi][ni], af[mi], b2);
                }
        }
        __syncthreads();
    }

    // epilogue
#pragma unroll
    for (int mi = 0; mi < 4; mi++) {
        int r0 = by * 128 + wm * 64 + mi * 16 + g;
        int r1 = r0 + 8;
#pragma unroll
        for (int ni = 0; ni < 4; ni++) {
            int c = bx * 128 + wn * 32 + ni * 8 + 2 * t;
            float b0v = bias[c], b1v = bias[c + 1];
            float e00 = acc[mi][ni][0] + b0v, e01 = acc[mi][ni][1] + b1v;
            float e10 = acc[mi][ni][2] + b0v, e11 = acc[mi][ni][3] + b1v;
            if (mode == 0) {
                *(float2*)(Cout + (size_t)r0 * N + c) = make_float2(e00, e01);
                *(float2*)(Cout + (size_t)r1 * N + c) = make_float2(e10, e11);
            } else {
                int sidx = c >> 10, rem = c & 1023;
                int h = rem >> 6, d = rem & 63;           // d even
                __half* dst = (sidx == 0) ? g_qh : (sidx == 1) ? g_kh : g_vh;
                int b0i = r0 >> 11, t0 = r0 & 2047;
                int b1i = r1 >> 11, t1 = r1 & 2047;
                size_t i0 = ((((size_t)b0i << 4) + h) * SEQ + t0) * D_HEAD + d;
                size_t i1 = ((((size_t)b1i << 4) + h) * SEQ + t1) * D_HEAD + d;
                *(uint32_t*)&dst[i0] = pack_h2(e00, e01);
                *(uint32_t*)&dst[i1] = pack_h2(e10, e11);
            }
        }
    }
}

// ---------------------------------------------------------------------------
// Flash attention v2, fp16 mma (m16n8k16), register softmax, no P shuffles.
// Block = 128 q-rows of one (b,h); 8 warps x 16 rows.
// smem: 2 stages x (K[64][72] + V[64][72]) halves = 36864 B.
// Q staged transiently (128x72 halves = one stage) before the main loop.
// ---------------------------------------------------------------------------
#define KVSTR 72
#define KV_TILE_BYTES (64 * KVSTR * 2)              // 9216
#define ATT_STG (2 * KV_TILE_BYTES)                 // 18432
#define ATTN_SMEM_BYTES (2 * ATT_STG)               // 36864

__global__ __launch_bounds__(256, 2) void attn_f16()
{
    extern __shared__ __half sma[];
    const int tid  = threadIdx.x;
    const int warp = tid >> 5, lane = tid & 31;
    const int g = lane >> 2, t = lane & 3;
    const int h = blockIdx.y, b = blockIdx.z;
    const int q0 = blockIdx.x * 128;
    const int qb = warp * 16;

    const size_t base = (size_t)(b * N_HEADS + h) * SEQ * D_HEAD;
    const __half* qp = g_qh + base + (size_t)q0 * D_HEAD;
    const __half* kp = g_kh + base;
    const __half* vp = g_vh + base;
    const uint32_t smb = smem_u32(sma);

    // ldmatrix lane mappings
    const int lr = (lane & 7) + ((lane >> 3) & 1) * 8;  // standard (A, trans-B)
    const int lk = ((lane >> 4) & 1) * 8;
    const int sr = (lane & 7) + ((lane >> 4) & 1) * 8;  // S-mma K frags
    const int sk = ((lane >> 3) & 1) * 8;

    // ---- stage Q (128 x 64 halves) at stride 72, load frags, release smem
#pragma unroll
    for (int it = 0; it < 4; it++) {
        int c = tid + it * 256;
        int r = c >> 3, cl = (c & 7) * 8;
        cp_async16(smb + (r * KVSTR + cl) * 2, qp + (size_t)r * D_HEAD + cl);
    }
    CP_COMMIT();
    CP_WAIT(0);
    __syncthreads();

    uint32_t qf[4][4];
#pragma unroll
    for (int j = 0; j < 4; j++) {
        uint32_t addr = smb + ((qb + lr) * KVSTR + j * 16 + lk) * 2;
        ldsm_x4(qf[j][0], qf[j][1], qf[j][2], qf[j][3], addr);
    }
    __syncthreads();   // Q consumed; region becomes KV stage 0

    float oacc[8][4];
#pragma unroll
    for (int ni = 0; ni < 8; ni++)
#pragma unroll
        for (int e = 0; e < 4; e++) oacc[ni][e] = 0.f;
    float m0 = -1e30f, m1 = -1e30f, l0 = 0.f, l1 = 0.f;

    // KV cp.async mapping: 64 rows x 64 halves = 8 chunks/row, 2/thread each
    // prologue tile 0
    {
        uint32_t kb = smb, vb = smb + KV_TILE_BYTES;
#pragma unroll
        for (int it = 0; it < 2; it++) {
            int c = tid + it * 256;
            int r = c >> 3, cl = (c & 7) * 8;
            cp_async16(kb + (r * KVSTR + cl) * 2, kp + (size_t)r * D_HEAD + cl);
            cp_async16(vb + (r * KVSTR + cl) * 2, vp + (size_t)r * D_HEAD + cl);
        }
        CP_COMMIT();
    }

    const float scale = 0.125f;   // 1/sqrt(64)

    for (int kt = 0, s = 0; kt < SEQ / 64; kt++, s ^= 1) {
        if (kt + 1 < SEQ / 64) {
            int k0n = (kt + 1) * 64;
            uint32_t kb = smb + (s ^ 1) * ATT_STG;
            uint32_t vb = kb + KV_TILE_BYTES;
#pragma unroll
            for (int it = 0; it < 2; it++) {
                int c = tid + it * 256;
                int r = c >> 3, cl = (c & 7) * 8;
                cp_async16(kb + (r * KVSTR + cl) * 2, kp + (size_t)(k0n + r) * D_HEAD + cl);
                cp_async16(vb + (r * KVSTR + cl) * 2, vp + (size_t)(k0n + r) * D_HEAD + cl);
            }
            CP_COMMIT();
            CP_WAIT(1);
        } else {
            CP_WAIT(0);
        }
        __syncthreads();

        const uint32_t kBase = smb + s * ATT_STG;
        const uint32_t vBase = kBase + KV_TILE_BYTES;

        // ---- S = Q @ K^T : 4 k16 chunks x 8 n8 tiles
        float sacc[8][4];
#pragma unroll
        for (int ni = 0; ni < 8; ni++)
#pragma unroll
            for (int e = 0; e < 4; e++) sacc[ni][e] = 0.f;

#pragma unroll
        for (int j = 0; j < 4; j++) {
#pragma unroll
            for (int nh = 0; nh < 4; nh++) {           // n-tile pairs
                uint32_t r0, r1, r2, r3;
                uint32_t addr = kBase + ((16 * nh + sr) * KVSTR + j * 16 + sk) * 2;
                ldsm_x4(r0, r1, r2, r3, addr);
                uint32_t bA[2] = { r0, r1 }, bB[2] = { r2, r3 };
                mma_f16(sacc[2 * nh], qf[j], bA);
                mma_f16(sacc[2 * nh + 1], qf[j], bB);
            }
        }

        // ---- online softmax in registers (rows g and g+8)
        float mx0 = -1e30f, mx1 = -1e30f;
#pragma unroll
        for (int ni = 0; ni < 8; ni++) {
            mx0 = fmaxf(mx0, fmaxf(sacc[ni][0], sacc[ni][1]));
            mx1 = fmaxf(mx1, fmaxf(sacc[ni][2], sacc[ni][3]));
        }
        mx0 = fmaxf(mx0, __shfl_xor_sync(0xffffffffu, mx0, 1));
        mx0 = fmaxf(mx0, __shfl_xor_sync(0xffffffffu, mx0, 2));
        mx1 = fmaxf(mx1, __shfl_xor_sync(0xffffffffu, mx1, 1));
        mx1 = fmaxf(mx1, __shfl_xor_sync(0xffffffffu, mx1, 2));

        float mn0 = fmaxf(m0, mx0 * scale), mn1 = fmaxf(m1, mx1 * scale);
        float a0 = __expf(m0 - mn0), a1 = __expf(m1 - mn1);
        float rs0 = 0.f, rs1 = 0.f;
#pragma unroll
        for (int ni = 0; ni < 8; ni++) {
            sacc[ni][0] = __expf(fmaf(sacc[ni][0], scale, -mn0));
            sacc[ni][1] = __expf(fmaf(sacc[ni][1], scale, -mn0));
            sacc[ni][2] = __expf(fmaf(sacc[ni][2], scale, -mn1));
            sacc[ni][3] = __expf(fmaf(sacc[ni][3], scale, -mn1));
            rs0 += sacc[ni][0] + sacc[ni][1];
            rs1 += sacc[ni][2] + sacc[ni][3];
        }
        rs0 += __shfl_xor_sync(0xffffffffu, rs0, 1);
        rs0 += __shfl_xor_sync(0xffffffffu, rs0, 2);
        rs1 += __shfl_xor_sync(0xffffffffu, rs1, 1);
        rs1 += __shfl_xor_sync(0xffffffffu, rs1, 2);
        l0 = l0 * a0 + rs0; l1 = l1 * a1 + rs1;
        m0 = mn0; m1 = mn1;
#pragma unroll
        for (int ni = 0; ni < 8; ni++) {
            oacc[ni][0] *= a0; oacc[ni][1] *= a0;
            oacc[ni][2] *= a1; oacc[ni][3] *= a1;
        }

        // ---- O += P @ V : P A-frags pack directly from sacc (no shuffles)
#pragma unroll
        for (int j = 0; j < 4; j++) {                   // kpos k16 chunks
            uint32_t pf[4];
            pf[0] = pack_h2(sacc[2 * j][0],     sacc[2 * j][1]);
            pf[1] = pack_h2(sacc[2 * j][2],     sacc[2 * j][3]);
            pf[2] = pack_h2(sacc[2 * j + 1][0], sacc[2 * j + 1][1]);
            pf[3] = pack_h2(sacc[2 * j + 1][2], sacc[2 * j + 1][3]);
#pragma unroll
            for (int ng = 0; ng < 4; ng++) {            // d n16 groups
                uint32_t r0, r1, r2, r3;
                uint32_t addr = vBase + ((j * 16 + lr) * KVSTR + ng * 16 + lk) * 2;
                ldsm_x4_t(r0, r1, r2, r3, addr);
                uint32_t bA[2] = { r0, r1 }, bB[2] = { r2, r3 };
                mma_f16(oacc[2 * ng], pf, bA);
                mma_f16(oacc[2 * ng + 1], pf, bB);
            }
        }
        __syncthreads();
    }

    // ---- normalize, convert to half, write g_attnh [B,T,C]
    {
        float li0 = 1.0f / l0, li1 = 1.0f / l1;
        int r0 = q0 + qb + g, r1 = r0 + 8;
#pragma unroll
        for (int ni = 0; ni < 8; ni++) {
            int c = ni * 8 + 2 * t;
            size_t i0 = ((size_t)b * SEQ + r0) * D_MODEL + h * D_HEAD + c;
            size_t i1 = ((size_t)b * SEQ + r1) * D_MODEL + h * D_HEAD + c;
            *(uint32_t*)&g_attnh[i0] = pack_h2(oacc[ni][0] * li0, oacc[ni][1] * li0);
            *(uint32_t*)&g_attnh[i1] = pack_h2(oacc[ni][2] * li1, oacc[ni][3] * li1);
        }
    }
}

// ---------------------------------------------------------------------------
// Launch
// ---------------------------------------------------------------------------
extern "C" void kernel_launch(void* const* d_in, const int* in_sizes, int n_in,
                              void* d_out, int out_size)
{
    const float* x     = (const float*)d_in[0];
    const float* w_qkv = (const float*)d_in[1];
    const float* b_qkv = (const float*)d_in[2];
    const float* w_out = (const float*)d_in[3];
    const float* b_out = (const float*)d_in[4];
    float* out = (float*)d_out;

    static bool attr_set = false;
    if (!attr_set) {
        cudaFuncSetAttribute(attn_f16,
                             cudaFuncAttributeMaxDynamicSharedMemorySize,
                             ATTN_SMEM_BYTES);
        cudaFuncSetAttribute(gemm_f16,
                             cudaFuncAttributeMaxDynamicSharedMemorySize,
                             GEMM_SMEM_BYTES);
        attr_set = true;
    }

    // 0) f32 -> f16 converts
    f2h_kernel<<<(BATCH * SEQ * D_MODEL / 4 + 255) / 256, 256>>>(
        (const float4*)x, 0, BATCH * SEQ * D_MODEL / 4);
    f2h_kernel<<<(D_MODEL * 3 * D_MODEL / 4 + 255) / 256, 256>>>(
        (const float4*)w_qkv, 1, D_MODEL * 3 * D_MODEL / 4);
    f2h_kernel<<<(D_MODEL * D_MODEL / 4 + 255) / 256, 256>>>(
        (const float4*)w_out, 2, D_MODEL * D_MODEL / 4);

    // 1) QKV projection + scatter to half [B,H,T,Dh]
    gemm_f16<<<dim3(3 * D_MODEL / 128, BATCH * SEQ / 128), 256, GEMM_SMEM_BYTES>>>(
        b_qkv, nullptr, 3 * D_MODEL, D_MODEL, 1);

    // 2) flash attention -> g_attnh [B,T,C] half
    attn_f16<<<dim3(SEQ / 128, N_HEADS, BATCH), 256, ATTN_SMEM_BYTES>>>();

    // 3) output projection -> d_out fp32
    gemm_f16<<<dim3(D_MODEL / 128, BATCH * SEQ / 128), 256, GEMM_SMEM_BYTES>>>(
        b_out, out, D_MODEL, D_MODEL, 0);
}

// round 8
// speedup vs baseline: 7.5480x; 1.0199x over previous
#include <cuda_runtime.h>
#include <cuda_fp16.h>
#include <cstdint>

#define D_MODEL 1024
#define N_HEADS 16
#define D_HEAD  64
#define BATCH   4
#define SEQ     2048

// Scratch (allocation-free rule: __device__ globals), fp16 working set
__device__ __align__(16) __half g_xh[BATCH * SEQ * D_MODEL];
__device__ __align__(16) __half g_wqkvh[D_MODEL * 3 * D_MODEL];
__device__ __align__(16) __half g_wouth[D_MODEL * D_MODEL];
__device__ __align__(16) __half g_qh[BATCH * N_HEADS * SEQ * D_HEAD];
__device__ __align__(16) __half g_kh[BATCH * N_HEADS * SEQ * D_HEAD];
__device__ __align__(16) __half g_vh[BATCH * N_HEADS * SEQ * D_HEAD];
__device__ __align__(16) __half g_attnh[BATCH * SEQ * D_MODEL];

// ---------------------------------------------------------------------------
// helpers
// ---------------------------------------------------------------------------
__device__ __forceinline__ uint32_t smem_u32(const void* p) {
    return (uint32_t)__cvta_generic_to_shared(p);
}
__device__ __forceinline__ void cp_async16(uint32_t dst, const void* src) {
    asm volatile("cp.async.cg.shared.global [%0], [%1], 16;" :: "r"(dst), "l"(src));
}
#define CP_COMMIT() asm volatile("cp.async.commit_group;")
#define CP_WAIT(n)  asm volatile("cp.async.wait_group %0;" :: "n"(n))

__device__ __forceinline__ uint32_t pack_h2(float a, float b) {
    __half2 h = __floats2half2_rn(a, b);
    return *(uint32_t*)&h;
}
__device__ __forceinline__ void ldsm_x4(uint32_t& r0, uint32_t& r1,
                                        uint32_t& r2, uint32_t& r3, uint32_t a) {
    asm volatile("ldmatrix.sync.aligned.m8n8.x4.shared.b16 {%0,%1,%2,%3}, [%4];"
                 : "=r"(r0), "=r"(r1), "=r"(r2), "=r"(r3) : "r"(a));
}
__device__ __forceinline__ void ldsm_x4_t(uint32_t& r0, uint32_t& r1,
                                          uint32_t& r2, uint32_t& r3, uint32_t a) {
    asm volatile("ldmatrix.sync.aligned.m8n8.x4.trans.shared.b16 {%0,%1,%2,%3}, [%4];"
                 : "=r"(r0), "=r"(r1), "=r"(r2), "=r"(r3) : "r"(a));
}
__device__ __forceinline__ void mma_f16(float c[4], const uint32_t a[4],
                                        const uint32_t b[2]) {
    asm volatile(
        "mma.sync.aligned.m16n8k16.row.col.f32.f16.f16.f32 "
        "{%0,%1,%2,%3}, {%4,%5,%6,%7}, {%8,%9}, {%0,%1,%2,%3};"
        : "+f"(c[0]), "+f"(c[1]), "+f"(c[2]), "+f"(c[3])
        : "r"(a[0]), "r"(a[1]), "r"(a[2]), "r"(a[3]), "r"(b[0]), "r"(b[1]));
}

// ---------------------------------------------------------------------------
// f32 -> f16 convert pre-pass. which: 0=x, 1=w_qkv, 2=w_out
// ---------------------------------------------------------------------------
__global__ void f2h_kernel(const float4* __restrict__ src, int which, int n4)
{
    int i = blockIdx.x * blockDim.x + threadIdx.x;
    if (i >= n4) return;
    uint2* dst = (which == 0) ? (uint2*)g_xh
               : (which == 1) ? (uint2*)g_wqkvh : (uint2*)g_wouth;
    float4 v = src[i];
    uint2 o;
    o.x = pack_h2(v.x, v.y);
    o.y = pack_h2(v.z, v.w);
    dst[i] = o;
}

// ---------------------------------------------------------------------------
// fp16 GEMM: C[M,N] = A[M,K] @ B[K,N] + bias (fp32 bias/acc)
// BM=BN=128, BK=32, 256 threads = 8 warps (2 m x 4 n), warp tile 64x32.
// 3-stage cp.async ring, ONE __syncthreads per k-iter.
// ---------------------------------------------------------------------------
#define ASTR 40
#define BSTR 136
#define A_BYTES (128 * ASTR * 2)     // 10240
#define B_BYTES (32 * BSTR * 2)      // 8704
#define STG_BYTES (A_BYTES + B_BYTES)
#define NSTG 3
#define GEMM_SMEM_BYTES (NSTG * STG_BYTES)

__global__ __launch_bounds__(256, 2) void gemm_f16(
    const float* __restrict__ bias, float* __restrict__ Cout,
    int N, int K, int mode)
{
    extern __shared__ __half smg[];
    const __half* A = (mode == 1) ? g_xh : g_attnh;
    const __half* B = (mode == 1) ? g_wqkvh : g_wouth;

    const int tid  = threadIdx.x;
    const int warp = tid >> 5, lane = tid & 31;
    const int g = lane >> 2, t = lane & 3;
    const int wm = warp >> 2;
    const int wn = warp & 3;
    const int bx = blockIdx.x, by = blockIdx.y;

    const __half* Ab = A + (size_t)by * 128 * K;
    const __half* Bb = B + (size_t)bx * 128;
    const uint32_t smb = smem_u32(smg);

    const int lr = (lane & 7) + ((lane >> 3) & 1) * 8;
    const int lk = ((lane >> 4) & 1) * 8;

    const int KT = K / 32;

    float acc[4][4][4];
#pragma unroll
    for (int mi = 0; mi < 4; mi++)
#pragma unroll
        for (int ni = 0; ni < 4; ni++)
#pragma unroll
            for (int e = 0; e < 4; e++) acc[mi][ni][e] = 0.f;

    auto load_tile = [&](int kt, int s) {
        uint32_t ab = smb + s * STG_BYTES, bb = ab + A_BYTES;
#pragma unroll
        for (int it = 0; it < 2; it++) {
            int c = tid + it * 256;
            int r = c >> 2, cl = (c & 3) * 8;
            cp_async16(ab + (r * ASTR + cl) * 2, Ab + (size_t)r * K + kt * 32 + cl);
        }
#pragma unroll
        for (int it = 0; it < 2; it++) {
            int c = tid + it * 256;
            int r = c >> 4, cl = (c & 15) * 8;
            cp_async16(bb + (r * BSTR + cl) * 2, Bb + (size_t)(kt * 32 + r) * N + cl);
        }
        CP_COMMIT();
    };

    load_tile(0, 0);
    load_tile(1, 1);

    for (int kt = 0; kt < KT; kt++) {
        const int s = kt % NSTG;
        if (kt + 1 < KT) CP_WAIT(1); else CP_WAIT(0);
        __syncthreads();
        if (kt + 2 < KT) load_tile(kt + 2, (kt + 2) % NSTG);

        const uint32_t aBase = smb + s * STG_BYTES;
        const uint32_t bBase = aBase + A_BYTES;

#pragma unroll
        for (int kk = 0; kk < 2; kk++) {
            uint32_t af[4][4];
#pragma unroll
            for (int mi = 0; mi < 4; mi++) {
                uint32_t addr = aBase +
                    ((wm * 64 + mi * 16 + lr) * ASTR + kk * 16 + lk) * 2;
                ldsm_x4(af[mi][0], af[mi][1], af[mi][2], af[mi][3], addr);
            }
            uint32_t bf[2][4];
#pragma unroll
            for (int ngi = 0; ngi < 2; ngi++) {
                uint32_t addr = bBase +
                    ((kk * 16 + lr) * BSTR + wn * 32 + ngi * 16 + lk) * 2;
                ldsm_x4_t(bf[ngi][0], bf[ngi][1], bf[ngi][2], bf[ngi][3], addr);
            }
#pragma unroll
            for (int mi = 0; mi < 4; mi++)
#pragma unroll
                for (int ni = 0; ni < 4; ni++) {
                    uint32_t b2[2] = { bf[ni >> 1][(ni & 1) * 2],
                                       bf[ni >> 1][(ni & 1) * 2 + 1] };
                    mma_f16(acc[mi][ni], af[mi], b2);
                }
        }
    }

    // epilogue
#pragma unroll
    for (int mi = 0; mi < 4; mi++) {
        int r0 = by * 128 + wm * 64 + mi * 16 + g;
        int r1 = r0 + 8;
#pragma unroll
        for (int ni = 0; ni < 4; ni++) {
            int c = bx * 128 + wn * 32 + ni * 8 + 2 * t;
            float b0v = bias[c], b1v = bias[c + 1];
            float e00 = acc[mi][ni][0] + b0v, e01 = acc[mi][ni][1] + b1v;
            float e10 = acc[mi][ni][2] + b0v, e11 = acc[mi][ni][3] + b1v;
            if (mode == 0) {
                *(float2*)(Cout + (size_t)r0 * N + c) = make_float2(e00, e01);
                *(float2*)(Cout + (size_t)r1 * N + c) = make_float2(e10, e11);
            } else {
                int sidx = c >> 10, rem = c & 1023;
                int h = rem >> 6, d = rem & 63;
                __half* dst = (sidx == 0) ? g_qh : (sidx == 1) ? g_kh : g_vh;
                int b0i = r0 >> 11, t0 = r0 & 2047;
                int b1i = r1 >> 11, t1 = r1 & 2047;
                size_t i0 = ((((size_t)b0i << 4) + h) * SEQ + t0) * D_HEAD + d;
                size_t i1 = ((((size_t)b1i << 4) + h) * SEQ + t1) * D_HEAD + d;
                *(uint32_t*)&dst[i0] = pack_h2(e00, e01);
                *(uint32_t*)&dst[i1] = pack_h2(e10, e11);
            }
        }
    }
}

// ---------------------------------------------------------------------------
// Flash attention v2, fp16 mma, register softmax; 3-stage KV ring, one
// barrier per KV tile.
// ---------------------------------------------------------------------------
#define KVSTR 72
#define KV_TILE_BYTES (64 * KVSTR * 2)              // 9216
#define ATT_STG (2 * KV_TILE_BYTES)                 // 18432 (K+V)
#define ATTN_SMEM_BYTES (NSTG * ATT_STG)            // 55296

__global__ __launch_bounds__(256, 2) void attn_f16()
{
    extern __shared__ __half sma[];
    const int tid  = threadIdx.x;
    const int warp = tid >> 5, lane = tid & 31;
    const int g = lane >> 2, t = lane & 3;
    const int h = blockIdx.y, b = blockIdx.z;
    const int q0 = blockIdx.x * 128;
    const int qb = warp * 16;

    const size_t base = (size_t)(b * N_HEADS + h) * SEQ * D_HEAD;
    const __half* qp = g_qh + base + (size_t)q0 * D_HEAD;
    const __half* kp = g_kh + base;
    const __half* vp = g_vh + base;
    const uint32_t smb = smem_u32(sma);

    const int lr = (lane & 7) + ((lane >> 3) & 1) * 8;
    const int lk = ((lane >> 4) & 1) * 8;
    const int sr = (lane & 7) + ((lane >> 4) & 1) * 8;
    const int sk = ((lane >> 3) & 1) * 8;

    // ---- stage Q (128 x 64 halves) at stride 72 in stage-0 region
#pragma unroll
    for (int it = 0; it < 4; it++) {
        int c = tid + it * 256;
        int r = c >> 3, cl = (c & 7) * 8;
        cp_async16(smb + (r * KVSTR + cl) * 2, qp + (size_t)r * D_HEAD + cl);
    }
    CP_COMMIT();
    CP_WAIT(0);
    __syncthreads();

    uint32_t qf[4][4];
#pragma unroll
    for (int j = 0; j < 4; j++) {
        uint32_t addr = smb + ((qb + lr) * KVSTR + j * 16 + lk) * 2;
        ldsm_x4(qf[j][0], qf[j][1], qf[j][2], qf[j][3], addr);
    }
    __syncthreads();   // Q consumed; region becomes KV ring

    float oacc[8][4];
#pragma unroll
    for (int ni = 0; ni < 8; ni++)
#pragma unroll
        for (int e = 0; e < 4; e++) oacc[ni][e] = 0.f;
    float m0 = -1e30f, m1 = -1e30f, l0 = 0.f, l1 = 0.f;

    auto load_kv = [&](int kt, int s) {
        int k0n = kt * 64;
        uint32_t kb = smb + s * ATT_STG;
        uint32_t vb = kb + KV_TILE_BYTES;
#pragma unroll
        for (int it = 0; it < 2; it++) {
            int c = tid + it * 256;
            int r = c >> 3, cl = (c & 7) * 8;
            cp_async16(kb + (r * KVSTR + cl) * 2, kp + (size_t)(k0n + r) * D_HEAD + cl);
            cp_async16(vb + (r * KVSTR + cl) * 2, vp + (size_t)(k0n + r) * D_HEAD + cl);
        }
        CP_COMMIT();
    };

    load_kv(0, 0);
    load_kv(1, 1);

    const float scale = 0.125f;
    const int NT = SEQ / 64;

    for (int kt = 0; kt < NT; kt++) {
        const int s = kt % NSTG;
        if (kt + 1 < NT) CP_WAIT(1); else CP_WAIT(0);
        __syncthreads();
        if (kt + 2 < NT) load_kv(kt + 2, (kt + 2) % NSTG);

        const uint32_t kBase = smb + s * ATT_STG;
        const uint32_t vBase = kBase + KV_TILE_BYTES;

        // ---- S = Q @ K^T
        float sacc[8][4];
#pragma unroll
        for (int ni = 0; ni < 8; ni++)
#pragma unroll
            for (int e = 0; e < 4; e++) sacc[ni][e] = 0.f;

#pragma unroll
        for (int j = 0; j < 4; j++) {
#pragma unroll
            for (int nh = 0; nh < 4; nh++) {
                uint32_t r0, r1, r2, r3;
                uint32_t addr = kBase + ((16 * nh + sr) * KVSTR + j * 16 + sk) * 2;
                ldsm_x4(r0, r1, r2, r3, addr);
                uint32_t bA[2] = { r0, r1 }, bB[2] = { r2, r3 };
                mma_f16(sacc[2 * nh], qf[j], bA);
                mma_f16(sacc[2 * nh + 1], qf[j], bB);
            }
        }

        // ---- online softmax in registers
        float mx0 = -1e30f, mx1 = -1e30f;
#pragma unroll
        for (int ni = 0; ni < 8; ni++) {
            mx0 = fmaxf(mx0, fmaxf(sacc[ni][0], sacc[ni][1]));
            mx1 = fmaxf(mx1, fmaxf(sacc[ni][2], sacc[ni][3]));
        }
        mx0 = fmaxf(mx0, __shfl_xor_sync(0xffffffffu, mx0, 1));
        mx0 = fmaxf(mx0, __shfl_xor_sync(0xffffffffu, mx0, 2));
        mx1 = fmaxf(mx1, __shfl_xor_sync(0xffffffffu, mx1, 1));
        mx1 = fmaxf(mx1, __shfl_xor_sync(0xffffffffu, mx1, 2));

        float mn0 = fmaxf(m0, mx0 * scale), mn1 = fmaxf(m1, mx1 * scale);
        float a0 = __expf(m0 - mn0), a1 = __expf(m1 - mn1);
        float rs0 = 0.f, rs1 = 0.f;
#pragma unroll
        for (int ni = 0; ni < 8; ni++) {
            sacc[ni][0] = __expf(fmaf(sacc[ni][0], scale, -mn0));
            sacc[ni][1] = __expf(fmaf(sacc[ni][1], scale, -mn0));
            sacc[ni][2] = __expf(fmaf(sacc[ni][2], scale, -mn1));
            sacc[ni][3] = __expf(fmaf(sacc[ni][3], scale, -mn1));
            rs0 += sacc[ni][0] + sacc[ni][1];
            rs1 += sacc[ni][2] + sacc[ni][3];
        }
        rs0 += __shfl_xor_sync(0xffffffffu, rs0, 1);
        rs0 += __shfl_xor_sync(0xffffffffu, rs0, 2);
        rs1 += __shfl_xor_sync(0xffffffffu, rs1, 1);
        rs1 += __shfl_xor_sync(0xffffffffu, rs1, 2);
        l0 = l0 * a0 + rs0; l1 = l1 * a1 + rs1;
        m0 = mn0; m1 = mn1;
#pragma unroll
        for (int ni = 0; ni < 8; ni++) {
            oacc[ni][0] *= a0; oacc[ni][1] *= a0;
            oacc[ni][2] *= a1; oacc[ni][3] *= a1;
        }

        // ---- O += P @ V
#pragma unroll
        for (int j = 0; j < 4; j++) {
            uint32_t pf[4];
            pf[0] = pack_h2(sacc[2 * j][0],     sacc[2 * j][1]);
            pf[1] = pack_h2(sacc[2 * j][2],     sacc[2 * j][3]);
            pf[2] = pack_h2(sacc[2 * j + 1][0], sacc[2 * j + 1][1]);
            pf[3] = pack_h2(sacc[2 * j + 1][2], sacc[2 * j + 1][3]);
#pragma unroll
            for (int ng = 0; ng < 4; ng++) {
                uint32_t r0, r1, r2, r3;
                uint32_t addr = vBase + ((j * 16 + lr) * KVSTR + ng * 16 + lk) * 2;
                ldsm_x4_t(r0, r1, r2, r3, addr);
                uint32_t bA[2] = { r0, r1 }, bB[2] = { r2, r3 };
                mma_f16(oacc[2 * ng], pf, bA);
                mma_f16(oacc[2 * ng + 1], pf, bB);
            }
        }
    }

    // ---- normalize, convert to half, write g_attnh [B,T,C]
    {
        float li0 = 1.0f / l0, li1 = 1.0f / l1;
        int r0 = q0 + qb + g, r1 = r0 + 8;
#pragma unroll
        for (int ni = 0; ni < 8; ni++) {
            int c = ni * 8 + 2 * t;
            size_t i0 = ((size_t)b * SEQ + r0) * D_MODEL + h * D_HEAD + c;
            size_t i1 = ((size_t)b * SEQ + r1) * D_MODEL + h * D_HEAD + c;
            *(uint32_t*)&g_attnh[i0] = pack_h2(oacc[ni][0] * li0, oacc[ni][1] * li0);
            *(uint32_t*)&g_attnh[i1] = pack_h2(oacc[ni][2] * li1, oacc[ni][3] * li1);
        }
    }
}

// ---------------------------------------------------------------------------
// Launch
// ---------------------------------------------------------------------------
extern "C" void kernel_launch(void* const* d_in, const int* in_sizes, int n_in,
                              void* d_out, int out_size)
{
    const float* x     = (const float*)d_in[0];
    const float* w_qkv = (const float*)d_in[1];
    const float* b_qkv = (const float*)d_in[2];
    const float* w_out = (const float*)d_in[3];
    const float* b_out = (const float*)d_in[4];
    float* out = (float*)d_out;

    static bool attr_set = false;
    if (!attr_set) {
        cudaFuncSetAttribute(attn_f16,
                             cudaFuncAttributeMaxDynamicSharedMemorySize,
                             ATTN_SMEM_BYTES);
        cudaFuncSetAttribute(gemm_f16,
                             cudaFuncAttributeMaxDynamicSharedMemorySize,
                             GEMM_SMEM_BYTES);
        attr_set = true;
    }

    // 0) f32 -> f16 converts
    f2h_kernel<<<(BATCH * SEQ * D_MODEL / 4 + 255) / 256, 256>>>(
        (const float4*)x, 0, BATCH * SEQ * D_MODEL / 4);
    f2h_kernel<<<(D_MODEL * 3 * D_MODEL / 4 + 255) / 256, 256>>>(
        (const float4*)w_qkv, 1, D_MODEL * 3 * D_MODEL / 4);
    f2h_kernel<<<(D_MODEL * D_MODEL / 4 + 255) / 256, 256>>>(
        (const float4*)w_out, 2, D_MODEL * D_MODEL / 4);

    // 1) QKV projection + scatter to half [B,H,T,Dh]
    gemm_f16<<<dim3(3 * D_MODEL / 128, BATCH * SEQ / 128), 256, GEMM_SMEM_BYTES>>>(
        b_qkv, nullptr, 3 * D_MODEL, D_MODEL, 1);

    // 2) flash attention -> g_attnh [B,T,C] half
    attn_f16<<<dim3(SEQ / 128, N_HEADS, BATCH), 256, ATTN_SMEM_BYTES>>>();

    // 3) output projection -> d_out fp32
    gemm_f16<<<dim3(D_MODEL / 128, BATCH * SEQ / 128), 256, GEMM_SMEM_BYTES>>>(
        b_out, out, D_MODEL, D_MODEL, 0);
}

// round 9
// speedup vs baseline: 7.6707x; 1.0163x over previous
#include <cuda_runtime.h>
#include <cuda_fp16.h>
#include <cstdint>

#define D_MODEL 1024
#define N_HEADS 16
#define D_HEAD  64
#define BATCH   4
#define SEQ     2048

// Scratch (allocation-free rule: __device__ globals), fp16 working set
__device__ __align__(16) __half g_xh[BATCH * SEQ * D_MODEL];
__device__ __align__(16) __half g_wqkvh[D_MODEL * 3 * D_MODEL];
__device__ __align__(16) __half g_wouth[D_MODEL * D_MODEL];
__device__ __align__(16) __half g_qh[BATCH * N_HEADS * SEQ * D_HEAD];
__device__ __align__(16) __half g_kh[BATCH * N_HEADS * SEQ * D_HEAD];
__device__ __align__(16) __half g_vh[BATCH * N_HEADS * SEQ * D_HEAD];
__device__ __align__(16) __half g_attnh[BATCH * SEQ * D_MODEL];

// ---------------------------------------------------------------------------
// helpers
// ---------------------------------------------------------------------------
__device__ __forceinline__ uint32_t smem_u32(const void* p) {
    return (uint32_t)__cvta_generic_to_shared(p);
}
__device__ __forceinline__ void cp_async16(uint32_t dst, const void* src) {
    asm volatile("cp.async.cg.shared.global [%0], [%1], 16;" :: "r"(dst), "l"(src));
}
#define CP_COMMIT() asm volatile("cp.async.commit_group;")
#define CP_WAIT(n)  asm volatile("cp.async.wait_group %0;" :: "n"(n))

__device__ __forceinline__ uint32_t pack_h2(float a, float b) {
    __half2 h = __floats2half2_rn(a, b);
    return *(uint32_t*)&h;
}
__device__ __forceinline__ void ldsm_x4(uint32_t& r0, uint32_t& r1,
                                        uint32_t& r2, uint32_t& r3, uint32_t a) {
    asm volatile("ldmatrix.sync.aligned.m8n8.x4.shared.b16 {%0,%1,%2,%3}, [%4];"
                 : "=r"(r0), "=r"(r1), "=r"(r2), "=r"(r3) : "r"(a));
}
__device__ __forceinline__ void ldsm_x4_t(uint32_t& r0, uint32_t& r1,
                                          uint32_t& r2, uint32_t& r3, uint32_t a) {
    asm volatile("ldmatrix.sync.aligned.m8n8.x4.trans.shared.b16 {%0,%1,%2,%3}, [%4];"
                 : "=r"(r0), "=r"(r1), "=r"(r2), "=r"(r3) : "r"(a));
}
__device__ __forceinline__ void mma_f16(float c[4], const uint32_t a[4],
                                        const uint32_t b[2]) {
    asm volatile(
        "mma.sync.aligned.m16n8k16.row.col.f32.f16.f16.f32 "
        "{%0,%1,%2,%3}, {%4,%5,%6,%7}, {%8,%9}, {%0,%1,%2,%3};"
        : "+f"(c[0]), "+f"(c[1]), "+f"(c[2]), "+f"(c[3])
        : "r"(a[0]), "r"(a[1]), "r"(a[2]), "r"(a[3]), "r"(b[0]), "r"(b[1]));
}

// ---------------------------------------------------------------------------
// f32 -> f16 convert pre-pass. which: 0=x, 1=w_qkv, 2=w_out
// ---------------------------------------------------------------------------
__global__ void f2h_kernel(const float4* __restrict__ src, int which, int n4)
{
    int i = blockIdx.x * blockDim.x + threadIdx.x;
    if (i >= n4) return;
    uint2* dst = (which == 0) ? (uint2*)g_xh
               : (which == 1) ? (uint2*)g_wqkvh : (uint2*)g_wouth;
    float4 v = src[i];
    uint2 o;
    o.x = pack_h2(v.x, v.y);
    o.y = pack_h2(v.z, v.w);
    dst[i] = o;
}

// ---------------------------------------------------------------------------
// fp16 GEMM: C[M,N] = A[M,K] @ B[K,N] + bias (fp32 bias/acc)
// BM=BN=128, BK=64, 256 threads = 8 warps (2 m x 4 n), warp tile 64x32.
// 3-stage cp.async ring, one barrier per k-iter; 4 kk-slices per iter with
// rotating register fragment buffers (ldsm of slice kk+1 under mma of kk).
// ---------------------------------------------------------------------------
#define ASTR 72
#define BSTR 136
#define A_BYTES (128 * ASTR * 2)     // 18432
#define B_BYTES (64 * BSTR * 2)      // 17408
#define STG_BYTES (A_BYTES + B_BYTES)  // 35840
#define NSTG 3
#define GEMM_SMEM_BYTES (NSTG * STG_BYTES)   // 107520

__global__ __launch_bounds__(256, 2) void gemm_f16(
    const float* __restrict__ bias, float* __restrict__ Cout,
    int N, int K, int mode)
{
    extern __shared__ __half smg[];
    const __half* A = (mode == 1) ? g_xh : g_attnh;
    const __half* B = (mode == 1) ? g_wqkvh : g_wouth;

    const int tid  = threadIdx.x;
    const int warp = tid >> 5, lane = tid & 31;
    const int g = lane >> 2, t = lane & 3;
    const int wm = warp >> 2;
    const int wn = warp & 3;
    const int bx = blockIdx.x, by = blockIdx.y;

    const __half* Ab = A + (size_t)by * 128 * K;
    const __half* Bb = B + (size_t)bx * 128;
    const uint32_t smb = smem_u32(smg);

    const int lr = (lane & 7) + ((lane >> 3) & 1) * 8;
    const int lk = ((lane >> 4) & 1) * 8;

    const int KT = K / 64;

    float acc[4][4][4];
#pragma unroll
    for (int mi = 0; mi < 4; mi++)
#pragma unroll
        for (int ni = 0; ni < 4; ni++)
#pragma unroll
            for (int e = 0; e < 4; e++) acc[mi][ni][e] = 0.f;

    // cp.async tile loader (A: 128x64 halves, B: 64x128 halves)
    auto load_tile = [&](int kt, int s) {
        uint32_t ab = smb + s * STG_BYTES, bb = ab + A_BYTES;
#pragma unroll
        for (int it = 0; it < 4; it++) {
            int c = tid + it * 256;
            int r = c >> 3, cl = (c & 7) * 8;
            cp_async16(ab + (r * ASTR + cl) * 2, Ab + (size_t)r * K + kt * 64 + cl);
        }
#pragma unroll
        for (int it = 0; it < 4; it++) {
            int c = tid + it * 256;
            int r = c >> 4, cl = (c & 15) * 8;
            cp_async16(bb + (r * BSTR + cl) * 2, Bb + (size_t)(kt * 64 + r) * N + cl);
        }
        CP_COMMIT();
    };

    load_tile(0, 0);
    load_tile(1, 1);

    for (int kt = 0; kt < KT; kt++) {
        const int s = kt % NSTG;
        if (kt + 1 < KT) CP_WAIT(1); else CP_WAIT(0);
        __syncthreads();
        if (kt + 2 < KT) load_tile(kt + 2, (kt + 2) % NSTG);

        const uint32_t aBase = smb + s * STG_BYTES;
        const uint32_t bBase = aBase + A_BYTES;
        // per-warp invariant ldsm base addresses
        uint32_t aAddr[4], bAddr[2];
#pragma unroll
        for (int mi = 0; mi < 4; mi++)
            aAddr[mi] = aBase + ((wm * 64 + mi * 16 + lr) * ASTR + lk) * 2;
#pragma unroll
        for (int ngi = 0; ngi < 2; ngi++)
            bAddr[ngi] = bBase + (lr * BSTR + wn * 32 + ngi * 16 + lk) * 2;

        // rotating fragment buffers over 4 kk-slices
        uint32_t af[2][4][4], bf[2][2][4];
        auto load_frag = [&](int kk, int bsel) {
#pragma unroll
            for (int mi = 0; mi < 4; mi++)
                ldsm_x4(af[bsel][mi][0], af[bsel][mi][1],
                        af[bsel][mi][2], af[bsel][mi][3],
                        aAddr[mi] + kk * 32);                 // 16 halves
#pragma unroll
            for (int ngi = 0; ngi < 2; ngi++)
                ldsm_x4_t(bf[bsel][ngi][0], bf[bsel][ngi][1],
                          bf[bsel][ngi][2], bf[bsel][ngi][3],
                          bAddr[ngi] + kk * 16 * BSTR * 2);   // 16 rows
        };

        load_frag(0, 0);
#pragma unroll
        for (int kk = 0; kk < 4; kk++) {
            if (kk + 1 < 4) load_frag(kk + 1, (kk + 1) & 1);
            const int bs = kk & 1;
#pragma unroll
            for (int mi = 0; mi < 4; mi++)
#pragma unroll
                for (int ni = 0; ni < 4; ni++) {
                    uint32_t b2[2] = { bf[bs][ni >> 1][(ni & 1) * 2],
                                       bf[bs][ni >> 1][(ni & 1) * 2 + 1] };
                    mma_f16(acc[mi][ni], af[bs][mi], b2);
                }
        }
    }

    // epilogue
#pragma unroll
    for (int mi = 0; mi < 4; mi++) {
        int r0 = by * 128 + wm * 64 + mi * 16 + g;
        int r1 = r0 + 8;
#pragma unroll
        for (int ni = 0; ni < 4; ni++) {
            int c = bx * 128 + wn * 32 + ni * 8 + 2 * t;
            float b0v = bias[c], b1v = bias[c + 1];
            float e00 = acc[mi][ni][0] + b0v, e01 = acc[mi][ni][1] + b1v;
            float e10 = acc[mi][ni][2] + b0v, e11 = acc[mi][ni][3] + b1v;
            if (mode == 0) {
                *(float2*)(Cout + (size_t)r0 * N + c) = make_float2(e00, e01);
                *(float2*)(Cout + (size_t)r1 * N + c) = make_float2(e10, e11);
            } else {
                int sidx = c >> 10, rem = c & 1023;
                int h = rem >> 6, d = rem & 63;
                __half* dst = (sidx == 0) ? g_qh : (sidx == 1) ? g_kh : g_vh;
                int b0i = r0 >> 11, t0 = r0 & 2047;
                int b1i = r1 >> 11, t1 = r1 & 2047;
                size_t i0 = ((((size_t)b0i << 4) + h) * SEQ + t0) * D_HEAD + d;
                size_t i1 = ((((size_t)b1i << 4) + h) * SEQ + t1) * D_HEAD + d;
                *(uint32_t*)&dst[i0] = pack_h2(e00, e01);
                *(uint32_t*)&dst[i1] = pack_h2(e10, e11);
            }
        }
    }
}

// ---------------------------------------------------------------------------
// Flash attention v2, fp16 mma, register softmax; 3-stage KV ring, one
// barrier per KV tile.  (unchanged from R8 — passing)
// ---------------------------------------------------------------------------
#define KVSTR 72
#define KV_TILE_BYTES (64 * KVSTR * 2)              // 9216
#define ATT_STG (2 * KV_TILE_BYTES)                 // 18432 (K+V)
#define ATTN_SMEM_BYTES (NSTG * ATT_STG)            // 55296

__global__ __launch_bounds__(256, 2) void attn_f16()
{
    extern __shared__ __half sma[];
    const int tid  = threadIdx.x;
    const int warp = tid >> 5, lane = tid & 31;
    const int g = lane >> 2, t = lane & 3;
    const int h = blockIdx.y, b = blockIdx.z;
    const int q0 = blockIdx.x * 128;
    const int qb = warp * 16;

    const size_t base = (size_t)(b * N_HEADS + h) * SEQ * D_HEAD;
    const __half* qp = g_qh + base + (size_t)q0 * D_HEAD;
    const __half* kp = g_kh + base;
    const __half* vp = g_vh + base;
    const uint32_t smb = smem_u32(sma);

    const int lr = (lane & 7) + ((lane >> 3) & 1) * 8;
    const int lk = ((lane >> 4) & 1) * 8;
    const int sr = (lane & 7) + ((lane >> 4) & 1) * 8;
    const int sk = ((lane >> 3) & 1) * 8;

#pragma unroll
    for (int it = 0; it < 4; it++) {
        int c = tid + it * 256;
        int r = c >> 3, cl = (c & 7) * 8;
        cp_async16(smb + (r * KVSTR + cl) * 2, qp + (size_t)r * D_HEAD + cl);
    }
    CP_COMMIT();
    CP_WAIT(0);
    __syncthreads();

    uint32_t qf[4][4];
#pragma unroll
    for (int j = 0; j < 4; j++) {
        uint32_t addr = smb + ((qb + lr) * KVSTR + j * 16 + lk) * 2;
        ldsm_x4(qf[j][0], qf[j][1], qf[j][2], qf[j][3], addr);
    }
    __syncthreads();

    float oacc[8][4];
#pragma unroll
    for (int ni = 0; ni < 8; ni++)
#pragma unroll
        for (int e = 0; e < 4; e++) oacc[ni][e] = 0.f;
    float m0 = -1e30f, m1 = -1e30f, l0 = 0.f, l1 = 0.f;

    auto load_kv = [&](int kt, int s) {
        int k0n = kt * 64;
        uint32_t kb = smb + s * ATT_STG;
        uint32_t vb = kb + KV_TILE_BYTES;
#pragma unroll
        for (int it = 0; it < 2; it++) {
            int c = tid + it * 256;
            int r = c >> 3, cl = (c & 7) * 8;
            cp_async16(kb + (r * KVSTR + cl) * 2, kp + (size_t)(k0n + r) * D_HEAD + cl);
            cp_async16(vb + (r * KVSTR + cl) * 2, vp + (size_t)(k0n + r) * D_HEAD + cl);
        }
        CP_COMMIT();
    };

    load_kv(0, 0);
    load_kv(1, 1);

    const float scale = 0.125f;
    const int NT = SEQ / 64;

    for (int kt = 0; kt < NT; kt++) {
        const int s = kt % NSTG;
        if (kt + 1 < NT) CP_WAIT(1); else CP_WAIT(0);
        __syncthreads();
        if (kt + 2 < NT) load_kv(kt + 2, (kt + 2) % NSTG);

        const uint32_t kBase = smb + s * ATT_STG;
        const uint32_t vBase = kBase + KV_TILE_BYTES;

        float sacc[8][4];
#pragma unroll
        for (int ni = 0; ni < 8; ni++)
#pragma unroll
            for (int e = 0; e < 4; e++) sacc[ni][e] = 0.f;

#pragma unroll
        for (int j = 0; j < 4; j++) {
#pragma unroll
            for (int nh = 0; nh < 4; nh++) {
                uint32_t r0, r1, r2, r3;
                uint32_t addr = kBase + ((16 * nh + sr) * KVSTR + j * 16 + sk) * 2;
                ldsm_x4(r0, r1, r2, r3, addr);
                uint32_t bA[2] = { r0, r1 }, bB[2] = { r2, r3 };
                mma_f16(sacc[2 * nh], qf[j], bA);
                mma_f16(sacc[2 * nh + 1], qf[j], bB);
            }
        }

        float mx0 = -1e30f, mx1 = -1e30f;
#pragma unroll
        for (int ni = 0; ni < 8; ni++) {
            mx0 = fmaxf(mx0, fmaxf(sacc[ni][0], sacc[ni][1]));
            mx1 = fmaxf(mx1, fmaxf(sacc[ni][2], sacc[ni][3]));
        }
        mx0 = fmaxf(mx0, __shfl_xor_sync(0xffffffffu, mx0, 1));
        mx0 = fmaxf(mx0, __shfl_xor_sync(0xffffffffu, mx0, 2));
        mx1 = fmaxf(mx1, __shfl_xor_sync(0xffffffffu, mx1, 1));
        mx1 = fmaxf(mx1, __shfl_xor_sync(0xffffffffu, mx1, 2));

        float mn0 = fmaxf(m0, mx0 * scale), mn1 = fmaxf(m1, mx1 * scale);
        float a0 = __expf(m0 - mn0), a1 = __expf(m1 - mn1);
        float rs0 = 0.f, rs1 = 0.f;
#pragma unroll
        for (int ni = 0; ni < 8; ni++) {
            sacc[ni][0] = __expf(fmaf(sacc[ni][0], scale, -mn0));
            sacc[ni][1] = __expf(fmaf(sacc[ni][1], scale, -mn0));
            sacc[ni][2] = __expf(fmaf(sacc[ni][2], scale, -mn1));
            sacc[ni][3] = __expf(fmaf(sacc[ni][3], scale, -mn1));
            rs0 += sacc[ni][0] + sacc[ni][1];
            rs1 += sacc[ni][2] + sacc[ni][3];
        }
        rs0 += __shfl_xor_sync(0xffffffffu, rs0, 1);
        rs0 += __shfl_xor_sync(0xffffffffu, rs0, 2);
        rs1 += __shfl_xor_sync(0xffffffffu, rs1, 1);
        rs1 += __shfl_xor_sync(0xffffffffu, rs1, 2);
        l0 = l0 * a0 + rs0; l1 = l1 * a1 + rs1;
        m0 = mn0; m1 = mn1;
#pragma unroll
        for (int ni = 0; ni < 8; ni++) {
            oacc[ni][0] *= a0; oacc[ni][1] *= a0;
            oacc[ni][2] *= a1; oacc[ni][3] *= a1;
        }

#pragma unroll
        for (int j = 0; j < 4; j++) {
            uint32_t pf[4];
            pf[0] = pack_h2(sacc[2 * j][0],     sacc[2 * j][1]);
            pf[1] = pack_h2(sacc[2 * j][2],     sacc[2 * j][3]);
            pf[2] = pack_h2(sacc[2 * j + 1][0], sacc[2 * j + 1][1]);
            pf[3] = pack_h2(sacc[2 * j + 1][2], sacc[2 * j + 1][3]);
#pragma unroll
            for (int ng = 0; ng < 4; ng++) {
                uint32_t r0, r1, r2, r3;
                uint32_t addr = vBase + ((j * 16 + lr) * KVSTR + ng * 16 + lk) * 2;
                ldsm_x4_t(r0, r1, r2, r3, addr);
                uint32_t bA[2] = { r0, r1 }, bB[2] = { r2, r3 };
                mma_f16(oacc[2 * ng], pf, bA);
                mma_f16(oacc[2 * ng + 1], pf, bB);
            }
        }
    }

    {
        float li0 = 1.0f / l0, li1 = 1.0f / l1;
        int r0 = q0 + qb + g, r1 = r0 + 8;
#pragma unroll
        for (int ni = 0; ni < 8; ni++) {
            int c = ni * 8 + 2 * t;
            size_t i0 = ((size_t)b * SEQ + r0) * D_MODEL + h * D_HEAD + c;
            size_t i1 = ((size_t)b * SEQ + r1) * D_MODEL + h * D_HEAD + c;
            *(uint32_t*)&g_attnh[i0] = pack_h2(oacc[ni][0] * li0, oacc[ni][1] * li0);
            *(uint32_t*)&g_attnh[i1] = pack_h2(oacc[ni][2] * li1, oacc[ni][3] * li1);
        }
    }
}

// ---------------------------------------------------------------------------
// Launch
// ---------------------------------------------------------------------------
extern "C" void kernel_launch(void* const* d_in, const int* in_sizes, int n_in,
                              void* d_out, int out_size)
{
    const float* x     = (const float*)d_in[0];
    const float* w_qkv = (const float*)d_in[1];
    const float* b_qkv = (const float*)d_in[2];
    const float* w_out = (const float*)d_in[3];
    const float* b_out = (const float*)d_in[4];
    float* out = (float*)d_out;

    static bool attr_set = false;
    if (!attr_set) {
        cudaFuncSetAttribute(attn_f16,
                             cudaFuncAttributeMaxDynamicSharedMemorySize,
                             ATTN_SMEM_BYTES);
        cudaFuncSetAttribute(gemm_f16,
                             cudaFuncAttributeMaxDynamicSharedMemorySize,
                             GEMM_SMEM_BYTES);
        attr_set = true;
    }

    // 0) f32 -> f16 converts
    f2h_kernel<<<(BATCH * SEQ * D_MODEL / 4 + 255) / 256, 256>>>(
        (const float4*)x, 0, BATCH * SEQ * D_MODEL / 4);
    f2h_kernel<<<(D_MODEL * 3 * D_MODEL / 4 + 255) / 256, 256>>>(
        (const float4*)w_qkv, 1, D_MODEL * 3 * D_MODEL / 4);
    f2h_kernel<<<(D_MODEL * D_MODEL / 4 + 255) / 256, 256>>>(
        (const float4*)w_out, 2, D_MODEL * D_MODEL / 4);

    // 1) QKV projection + scatter to half [B,H,T,Dh]
    gemm_f16<<<dim3(3 * D_MODEL / 128, BATCH * SEQ / 128), 256, GEMM_SMEM_BYTES>>>(
        b_qkv, nullptr, 3 * D_MODEL, D_MODEL, 1);

    // 2) flash attention -> g_attnh [B,T,C] half
    attn_f16<<<dim3(SEQ / 128, N_HEADS, BATCH), 256, ATTN_SMEM_BYTES>>>();

    // 3) output projection -> d_out fp32
    gemm_f16<<<dim3(D_MODEL / 128, BATCH * SEQ / 128), 256, GEMM_SMEM_BYTES>>>(
        b_out, out, D_MODEL, D_MODEL, 0);
}